// round 4
// baseline (speedup 1.0000x reference)
#include <cuda_runtime.h>
#include <cstdint>
#include <cstddef>

// ---------------- problem constants ----------------
#define B_   8
#define T_   2048
#define C_   2048
#define H_   32
#define HS_  64
#define BT_  (B_*T_)          // 16384
#define CC_  (C_*C_)          // 4194304

// ---------------- scratch (device globals; no allocation) ----------------
__device__ float g_xk[BT_*(size_t)C_];
__device__ float g_xv[BT_*(size_t)C_];
__device__ float g_xr[BT_*(size_t)C_];
__device__ float g_xg[BT_*(size_t)C_];
__device__ float g_r [BT_*(size_t)C_];
__device__ float g_k [BT_*(size_t)C_];
__device__ float g_v [BT_*(size_t)C_];
__device__ float g_g [BT_*(size_t)C_];
__device__ float g_yng[BT_*(size_t)C_];
__device__ float g_W[5][CC_];   // tf32-rounded Wr,Wk,Wv,Wg,Wo

// ---------------- helpers ----------------
__device__ __forceinline__ float to_tf32(float x) {
    uint32_t o;
    asm("cvt.rna.tf32.f32 %0, %1;" : "=r"(o) : "f"(x));
    return __uint_as_float(o);
}

__device__ __forceinline__ void mma_tf32(float (&c)[4],
                                         const uint32_t (&a)[4],
                                         const uint32_t (&b)[2]) {
    asm volatile(
        "mma.sync.aligned.m16n8k8.row.col.f32.tf32.tf32.f32 "
        "{%0,%1,%2,%3}, {%4,%5,%6,%7}, {%8,%9}, {%0,%1,%2,%3};\n"
        : "+f"(c[0]), "+f"(c[1]), "+f"(c[2]), "+f"(c[3])
        : "r"(a[0]), "r"(a[1]), "r"(a[2]), "r"(a[3]),
          "r"(b[0]), "r"(b[1]));
}

// ---------------- weight rounding (fp32 -> tf32 bits) ----------------
__global__ void round_tf32_kernel(const float4* __restrict__ src,
                                  float4* __restrict__ dst, int n4) {
    int i = blockIdx.x * blockDim.x + threadIdx.x;
    if (i >= n4) return;
    float4 v = src[i];
    v.x = to_tf32(v.x); v.y = to_tf32(v.y);
    v.z = to_tf32(v.z); v.w = to_tf32(v.w);
    dst[i] = v;
}

// ---------------- token-shift mix: xk/xv/xr/xg (tf32-rounded) ----------------
__global__ void mix_kernel(const float4* __restrict__ x,
                           const float4* __restrict__ tmk,
                           const float4* __restrict__ tmv,
                           const float4* __restrict__ tmr,
                           const float4* __restrict__ tmg,
                           float4* __restrict__ xk, float4* __restrict__ xv,
                           float4* __restrict__ xr, float4* __restrict__ xg) {
    const int C4 = C_ / 4;
    int idx = blockIdx.x * blockDim.x + threadIdx.x;
    if (idx >= BT_ * C4) return;
    int c4 = idx % C4;
    int bt = idx / C4;
    int t  = bt % T_;
    float4 xc = x[idx];
    float4 xp = make_float4(0.f, 0.f, 0.f, 0.f);
    if (t != 0) xp = x[idx - C4];
    float4 mk = tmk[c4], mv = tmv[c4], mr = tmr[c4], mg = tmg[c4];
    // out = xp + m*(x - xp), rounded to tf32
    float4 o;
#define MIXC(dst, m) \
    o.x = to_tf32(fmaf(m.x, xc.x - xp.x, xp.x)); \
    o.y = to_tf32(fmaf(m.y, xc.y - xp.y, xp.y)); \
    o.z = to_tf32(fmaf(m.z, xc.z - xp.z, xp.z)); \
    o.w = to_tf32(fmaf(m.w, xc.w - xp.w, xp.w)); \
    dst[idx] = o;
    MIXC(xk, mk)
    MIXC(xv, mv)
    MIXC(xr, mr)
    MIXC(xg, mg)
#undef MIXC
}

// ---------------- tf32 GEMM: C[M,N] = A[M,K] @ B[K,N], M=16384,N=K=2048 ----
// BM=BN=128, BK=16, 256 threads (8 warps, 2x4), warp tile 64x32, mma 16n8k8.
// act: 0 = none, 1 = silu.
#define GM_  16384
#define GN_  2048
#define GK_  2048
#define BKT_ (GK_/16)   // 128 k-tiles

__global__ __launch_bounds__(256) void gemm_tf32_kernel(
        const float* __restrict__ A, const float* __restrict__ Bw,
        float* __restrict__ Cout, int act) {
    __shared__ __align__(16) float As[2][128 * 20];   // [row][k] pad 20
    __shared__ __align__(16) float Bs[2][16 * 136];   // [k][n]  pad 136

    const int tid  = threadIdx.x;
    const int lane = tid & 31;
    const int warp = tid >> 5;
    const int wm = (warp >> 2) * 64;   // warp row offset in tile
    const int wn = (warp & 3) * 32;    // warp col offset in tile
    const int bm = blockIdx.y * 128;
    const int bn = blockIdx.x * 128;

    float acc[4][4][4];
#pragma unroll
    for (int i = 0; i < 4; i++)
#pragma unroll
        for (int j = 0; j < 4; j++)
#pragma unroll
            for (int q = 0; q < 4; q++) acc[i][j][q] = 0.f;

    float4 ra[2], rb[2];

    auto load_g = [&](int kt) {
#pragma unroll
        for (int q = 0; q < 2; q++) {
            int f = tid + q * 256;
            int r = f >> 2, cs = f & 3;                 // A: 128 rows x 4 segs
            ra[q] = *(const float4*)&A[(size_t)(bm + r) * GK_ + kt * 16 + cs * 4];
            int kr = f >> 5, ns = f & 31;               // B: 16 rows x 32 segs
            rb[q] = *(const float4*)&Bw[(size_t)(kt * 16 + kr) * GN_ + bn + ns * 4];
        }
    };
    auto store_s = [&](int s) {
#pragma unroll
        for (int q = 0; q < 2; q++) {
            int f = tid + q * 256;
            int r = f >> 2, cs = f & 3;
            *(float4*)&As[s][r * 20 + cs * 4] = ra[q];
            int kr = f >> 5, ns = f & 31;
            *(float4*)&Bs[s][kr * 136 + ns * 4] = rb[q];
        }
    };

    load_g(0);
    store_s(0);
    __syncthreads();

    int s = 0;
    for (int kt = 0; kt < BKT_; kt++) {
        if (kt + 1 < BKT_) load_g(kt + 1);
        const int r0 = lane >> 2, c0 = lane & 3;
#pragma unroll
        for (int ks = 0; ks < 2; ks++) {
            uint32_t af[4][4], bf[4][2];
#pragma unroll
            for (int mt = 0; mt < 4; mt++) {
                int rr = wm + mt * 16 + r0;
                const float* as = As[s];
                af[mt][0] = __float_as_uint(as[(rr)     * 20 + ks * 8 + c0]);
                af[mt][1] = __float_as_uint(as[(rr + 8) * 20 + ks * 8 + c0]);
                af[mt][2] = __float_as_uint(as[(rr)     * 20 + ks * 8 + c0 + 4]);
                af[mt][3] = __float_as_uint(as[(rr + 8) * 20 + ks * 8 + c0 + 4]);
            }
#pragma unroll
            for (int nt = 0; nt < 4; nt++) {
                int cb = wn + nt * 8 + (lane >> 2);
                const float* bs = Bs[s];
                bf[nt][0] = __float_as_uint(bs[(ks * 8 + c0)     * 136 + cb]);
                bf[nt][1] = __float_as_uint(bs[(ks * 8 + c0 + 4) * 136 + cb]);
            }
#pragma unroll
            for (int mt = 0; mt < 4; mt++)
#pragma unroll
                for (int nt = 0; nt < 4; nt++)
                    mma_tf32(acc[mt][nt], af[mt], bf[nt]);
        }
        if (kt + 1 < BKT_) store_s(s ^ 1);
        __syncthreads();
        s ^= 1;
    }

    // epilogue
#pragma unroll
    for (int mt = 0; mt < 4; mt++) {
#pragma unroll
        for (int nt = 0; nt < 4; nt++) {
            int row = bm + wm + mt * 16 + (lane >> 2);
            int col = bn + wn + nt * 8 + (lane & 3) * 2;
            float v0 = acc[mt][nt][0], v1 = acc[mt][nt][1];
            float v2 = acc[mt][nt][2], v3 = acc[mt][nt][3];
            if (act == 1) {
                v0 = v0 / (1.f + expf(-v0));
                v1 = v1 / (1.f + expf(-v1));
                v2 = v2 / (1.f + expf(-v2));
                v3 = v3 / (1.f + expf(-v3));
            }
            *(float2*)&Cout[(size_t)row * GN_ + col]       = make_float2(v0, v1);
            *(float2*)&Cout[(size_t)(row + 8) * GN_ + col] = make_float2(v2, v3);
        }
    }
}

// ---------------- WKV5 recurrence + fused /8, groupnorm, *g -----------------
// One block per (b,h). 256 threads: thread = (ig in 0..3) x (j in 0..63).
// Thread owns S[i, j] for i in [ig*16, ig*16+16). y_t = r.S_prev + (sum r*u*k)*v.
__global__ __launch_bounds__(256) void wkv_kernel(
        const float* __restrict__ r, const float* __restrict__ k,
        const float* __restrict__ v, const float* __restrict__ g,
        const float* __restrict__ decay, const float* __restrict__ faaaa,
        const float* __restrict__ lnw, const float* __restrict__ lnb,
        float* __restrict__ yng) {
    __shared__ float sr[64], sk[64], sv[64], sruk[64];
    __shared__ float syp[256];
    __shared__ float sred[4];

    const int tid = threadIdx.x;
    const int bh = blockIdx.x;
    const int b = bh / H_, h = bh % H_;
    const int ig = tid >> 6;
    const int j  = tid & 63;

    float S[16], w16[16];
#pragma unroll
    for (int ii = 0; ii < 16; ii++) {
        S[ii] = 0.f;
        w16[ii] = expf(-expf(decay[h * 64 + ig * 16 + ii]));
    }
    float uu = 0.f;
    if (tid >= 192) uu = faaaa[h * 64 + (tid - 192)];
    float lw = 1.f, lb = 0.f;
    if (tid < 64) { lw = lnw[h * 64 + tid]; lb = lnb[h * 64 + tid]; }

    size_t base = (size_t)b * T_ * C_ + (size_t)h * 64;
    const float inv_div = 1.f / 8.f;

    for (int t = 0; t < T_; t++) {
        __syncthreads();                       // reuse smem from prev step
        if (tid < 64)       sr[tid]        = r[base + tid];
        else if (tid < 128) sk[tid - 64]   = k[base + (tid - 64)];
        else if (tid < 192) sv[tid - 128]  = v[base + (tid - 128)];
        else {
            int i2 = tid - 192;
            sruk[i2] = r[base + i2] * uu * k[base + i2];
        }
        __syncthreads();

        const float vj = sv[j];
        float yp = 0.f, cp = 0.f;
#pragma unroll
        for (int ii = 0; ii < 16; ii++) {
            float ri = sr[ig * 16 + ii];
            float ki = sk[ig * 16 + ii];
            yp = fmaf(ri, S[ii], yp);          // uses S BEFORE update
            S[ii] = fmaf(w16[ii], S[ii], ki * vj);
            cp += sruk[ig * 16 + ii];
        }
        yp = fmaf(cp, vj, yp);                 // + r.(u o k) v_j term
        syp[ig * 64 + j] = yp;
        __syncthreads();

        float yh = 0.f;
        if (tid < 64) {
            float y = syp[j] + syp[64 + j] + syp[128 + j] + syp[192 + j];
            yh = y * inv_div;
            float s1 = yh, s2 = yh * yh;
#pragma unroll
            for (int off = 16; off; off >>= 1) {
                s1 += __shfl_xor_sync(0xffffffffu, s1, off);
                s2 += __shfl_xor_sync(0xffffffffu, s2, off);
            }
            if ((tid & 31) == 0) {
                sred[(tid >> 5) * 2]     = s1;
                sred[(tid >> 5) * 2 + 1] = s2;
            }
        }
        __syncthreads();
        if (tid < 64) {
            float m1 = (sred[0] + sred[2]) * (1.f / 64.f);
            float m2 = (sred[1] + sred[3]) * (1.f / 64.f);
            float var = m2 - m1 * m1;
            float yn = (yh - m1) * rsqrtf(var + 1e-5f) * lw + lb;
            float o  = yn * g[base + tid];
            yng[base + tid] = to_tf32(o);      // pre-round for the Wo GEMM
        }
        base += C_;
    }
}

// ---------------- host launch ----------------
extern "C" void kernel_launch(void* const* d_in, const int* in_sizes, int n_in,
                              void* d_out, int out_size) {
    const float* x     = (const float*)d_in[0];
    const float* tmk   = (const float*)d_in[1];
    const float* tmv   = (const float*)d_in[2];
    const float* tmr   = (const float*)d_in[3];
    const float* tmg   = (const float*)d_in[4];
    const float* decay = (const float*)d_in[5];
    const float* faaaa = (const float*)d_in[6];
    const float* Wr    = (const float*)d_in[7];
    const float* Wk    = (const float*)d_in[8];
    const float* Wv    = (const float*)d_in[9];
    const float* Wg    = (const float*)d_in[10];
    const float* Wo    = (const float*)d_in[11];
    const float* lnw   = (const float*)d_in[12];
    const float* lnb   = (const float*)d_in[13];

    float *xk, *xv, *xr, *xg, *rr, *kk, *vv, *gg, *yng, *Wbuf;
    cudaGetSymbolAddress((void**)&xk,  g_xk);
    cudaGetSymbolAddress((void**)&xv,  g_xv);
    cudaGetSymbolAddress((void**)&xr,  g_xr);
    cudaGetSymbolAddress((void**)&xg,  g_xg);
    cudaGetSymbolAddress((void**)&rr,  g_r);
    cudaGetSymbolAddress((void**)&kk,  g_k);
    cudaGetSymbolAddress((void**)&vv,  g_v);
    cudaGetSymbolAddress((void**)&gg,  g_g);
    cudaGetSymbolAddress((void**)&yng, g_yng);
    cudaGetSymbolAddress((void**)&Wbuf, g_W);
    float* w0 = Wbuf + 0 * (size_t)CC_;
    float* w1 = Wbuf + 1 * (size_t)CC_;
    float* w2 = Wbuf + 2 * (size_t)CC_;
    float* w3 = Wbuf + 3 * (size_t)CC_;
    float* w4 = Wbuf + 4 * (size_t)CC_;

    // 1) round weights to tf32 bit patterns
    {
        int n4 = CC_ / 4;
        int grid = (n4 + 255) / 256;
        round_tf32_kernel<<<grid, 256>>>((const float4*)Wr, (float4*)w0, n4);
        round_tf32_kernel<<<grid, 256>>>((const float4*)Wk, (float4*)w1, n4);
        round_tf32_kernel<<<grid, 256>>>((const float4*)Wv, (float4*)w2, n4);
        round_tf32_kernel<<<grid, 256>>>((const float4*)Wg, (float4*)w3, n4);
        round_tf32_kernel<<<grid, 256>>>((const float4*)Wo, (float4*)w4, n4);
    }

    // 2) token-shift mixes (tf32-rounded)
    {
        int n4 = BT_ * (C_ / 4);
        int grid = (n4 + 255) / 256;
        mix_kernel<<<grid, 256>>>((const float4*)x,
                                  (const float4*)tmk, (const float4*)tmv,
                                  (const float4*)tmr, (const float4*)tmg,
                                  (float4*)xk, (float4*)xv,
                                  (float4*)xr, (float4*)xg);
    }

    // 3) projections (tf32 mma): r,k,v plain; g with silu
    dim3 gemm_grid(GN_ / 128, GM_ / 128);
    gemm_tf32_kernel<<<gemm_grid, 256>>>(xr, w0, rr, 0);
    gemm_tf32_kernel<<<gemm_grid, 256>>>(xk, w1, kk, 0);
    gemm_tf32_kernel<<<gemm_grid, 256>>>(xv, w2, vv, 0);
    gemm_tf32_kernel<<<gemm_grid, 256>>>(xg, w3, gg, 1);

    // 4) WKV recurrence + fused /8 + groupnorm + *g  -> yng (tf32-rounded)
    wkv_kernel<<<B_ * H_, 256>>>(rr, kk, vv, gg, decay, faaaa, lnw, lnb, yng);

    // 5) output projection
    gemm_tf32_kernel<<<gemm_grid, 256>>>(yng, w4, (float*)d_out, 0);
}

// round 6
// speedup vs baseline: 2.0405x; 2.0405x over previous
#include <cuda_runtime.h>
#include <cstdint>
#include <cstddef>

// ---------------- problem constants ----------------
#define B_   8
#define T_   2048
#define C_   2048
#define H_   32
#define HS_  64
#define BT_  (B_*T_)          // 16384
#define CC_  (C_*C_)          // 4194304

// ---------------- scratch (device globals; no allocation) ----------------
__device__ float g_xk[BT_*(size_t)C_];
__device__ float g_xv[BT_*(size_t)C_];
__device__ float g_xr[BT_*(size_t)C_];
__device__ float g_xg[BT_*(size_t)C_];
__device__ float g_r [BT_*(size_t)C_];
__device__ float g_k [BT_*(size_t)C_];
__device__ float g_v [BT_*(size_t)C_];
__device__ float g_g [BT_*(size_t)C_];
__device__ float g_yng[BT_*(size_t)C_];
__device__ float g_W[5][CC_];   // tf32-rounded Wr,Wk,Wv,Wg,Wo  (layout [K,N])

// ---------------- helpers ----------------
__device__ __forceinline__ float to_tf32(float x) {
    uint32_t o;
    asm("cvt.rna.tf32.f32 %0, %1;" : "=r"(o) : "f"(x));
    return __uint_as_float(o);
}

__device__ __forceinline__ uint32_t smem_u32(const void* p) {
    return (uint32_t)__cvta_generic_to_shared(p);
}

__device__ __forceinline__ void mma_tf32(float (&c)[4],
                                         const uint32_t (&a)[4],
                                         const uint32_t (&b)[2]) {
    asm volatile(
        "mma.sync.aligned.m16n8k8.row.col.f32.tf32.tf32.f32 "
        "{%0,%1,%2,%3}, {%4,%5,%6,%7}, {%8,%9}, {%0,%1,%2,%3};\n"
        : "+f"(c[0]), "+f"(c[1]), "+f"(c[2]), "+f"(c[3])
        : "r"(a[0]), "r"(a[1]), "r"(a[2]), "r"(a[3]),
          "r"(b[0]), "r"(b[1]));
}

// ---------------- weight rounding (fp32 -> tf32 bits) ----------------
__global__ void round_tf32_kernel(const float4* __restrict__ src,
                                  float4* __restrict__ dst, int n4) {
    int i = blockIdx.x * blockDim.x + threadIdx.x;
    if (i >= n4) return;
    float4 v = src[i];
    v.x = to_tf32(v.x); v.y = to_tf32(v.y);
    v.z = to_tf32(v.z); v.w = to_tf32(v.w);
    dst[i] = v;
}

// ---------------- token-shift mix: xk/xv/xr/xg (tf32-rounded) ----------------
__global__ void mix_kernel(const float4* __restrict__ x,
                           const float4* __restrict__ tmk,
                           const float4* __restrict__ tmv,
                           const float4* __restrict__ tmr,
                           const float4* __restrict__ tmg,
                           float4* __restrict__ xk, float4* __restrict__ xv,
                           float4* __restrict__ xr, float4* __restrict__ xg) {
    const int C4 = C_ / 4;
    int idx = blockIdx.x * blockDim.x + threadIdx.x;
    if (idx >= BT_ * C4) return;
    int c4 = idx % C4;
    int bt = idx / C4;
    int t  = bt % T_;
    float4 xc = x[idx];
    float4 xp = make_float4(0.f, 0.f, 0.f, 0.f);
    if (t != 0) xp = x[idx - C4];
    float4 mk = tmk[c4], mv = tmv[c4], mr = tmr[c4], mg = tmg[c4];
    float4 o;
#define MIXC(dst, m) \
    o.x = to_tf32(fmaf(m.x, xc.x - xp.x, xp.x)); \
    o.y = to_tf32(fmaf(m.y, xc.y - xp.y, xp.y)); \
    o.z = to_tf32(fmaf(m.z, xc.z - xp.z, xp.z)); \
    o.w = to_tf32(fmaf(m.w, xc.w - xp.w, xp.w)); \
    dst[idx] = o;
    MIXC(xk, mk)
    MIXC(xv, mv)
    MIXC(xr, mr)
    MIXC(xg, mg)
#undef MIXC
}

// ---------------- tf32 mma.sync GEMM with cp.async pipeline ------------------
// C[M=16384, N=2048] = A[M,K=2048] @ B[K,N]      (B row-major [K,N])
// BM=BN=128, BK=32, 3 stages, 256 threads (8 warps 2x4), warp tile 64x32.
// A smem: [128][36] floats (stride 36: banks 4g+t, conflict-free)
// B smem: [32][136] floats (stride 136: banks 8t+n, conflict-free)
#define GBM   128
#define GBN   128
#define GBK   32
#define NSTG  3
#define NTIL  (C_ / GBK)          // 64
#define AS_STRIDE 36
#define BS_STRIDE 136
#define AS_FLOATS (GBM * AS_STRIDE)            // 4608
#define BS_FLOATS (GBK * BS_STRIDE)            // 4352
#define STG_FLOATS (AS_FLOATS + BS_FLOATS)     // 8960
#define GEMM_SMEM (NSTG * STG_FLOATS * 4)      // 107520 bytes

__global__ __launch_bounds__(256, 2) void gemm_tf32_kernel(
        const float* __restrict__ Ag, const float* __restrict__ Bw,
        float* __restrict__ Cout, int act) {
    extern __shared__ float sm[];
    const uint32_t smb = smem_u32(sm);

    const int tid  = threadIdx.x;
    const int lane = tid & 31;
    const int warp = tid >> 5;
    const int wm = (warp >> 2) * 64;
    const int wn = (warp & 3) * 32;
    const int bm = blockIdx.y * GBM;
    const int bn = blockIdx.x * GBN;
    const int g  = lane >> 2;      // 0..7
    const int t  = lane & 3;       // 0..3

    float acc[4][4][4];
#pragma unroll
    for (int i = 0; i < 4; i++)
#pragma unroll
        for (int j = 0; j < 4; j++)
#pragma unroll
            for (int q = 0; q < 4; q++) acc[i][j][q] = 0.f;

    // cp.async geometry: A 1024 float4 (4/thread), B 1024 float4 (4/thread)
    const int ar  = tid >> 1;                 // with q*128: rows 0..127 (2 passes)
    const int ak4 = (tid & 1) * 4;            // float4 pairs... use simpler scheme:
    (void)ar; (void)ak4;

    auto issue_tile = [&](int kt) {
        const int s = kt % NSTG;
        const uint32_t sA = smb + (uint32_t)(s * STG_FLOATS) * 4u;
        const uint32_t sB = sA + AS_FLOATS * 4u;
#pragma unroll
        for (int q = 0; q < 4; q++) {
            int idx = tid + q * 256;
            int r  = idx >> 3;                // 0..127
            int k4 = idx & 7;                 // 0..7
            const float* gp = Ag + (size_t)(bm + r) * C_ + kt * GBK + k4 * 4;
            uint32_t so = sA + (uint32_t)(r * AS_STRIDE + k4 * 4) * 4u;
            asm volatile("cp.async.cg.shared.global [%0], [%1], 16;"
                         :: "r"(so), "l"(gp) : "memory");
        }
#pragma unroll
        for (int q = 0; q < 4; q++) {
            int idx = tid + q * 256;
            int kr = idx >> 5;                // 0..31
            int n4 = idx & 31;                // 0..31
            const float* gp = Bw + (size_t)(kt * GBK + kr) * C_ + bn + n4 * 4;
            uint32_t so = sB + (uint32_t)(kr * BS_STRIDE + n4 * 4) * 4u;
            asm volatile("cp.async.cg.shared.global [%0], [%1], 16;"
                         :: "r"(so), "l"(gp) : "memory");
        }
        asm volatile("cp.async.commit_group;" ::: "memory");
    };

    // prologue: stages 0..NSTG-2
    issue_tile(0);
    issue_tile(1);

#pragma unroll 1
    for (int kt = 0; kt < NTIL; kt++) {
        if (kt + NSTG - 1 < NTIL) {
            asm volatile("cp.async.wait_group %0;" :: "n"(NSTG - 2) : "memory");
        } else {
            asm volatile("cp.async.wait_group 0;" ::: "memory");
        }
        __syncthreads();
        if (kt + NSTG - 1 < NTIL) issue_tile(kt + NSTG - 1);

        const int s = kt % NSTG;
        const float* as = sm + s * STG_FLOATS;
        const float* bs = as + AS_FLOATS;

#pragma unroll
        for (int ks = 0; ks < 4; ks++) {
            uint32_t af[4][4], bf[4][2];
#pragma unroll
            for (int mt = 0; mt < 4; mt++) {
                int rr = wm + mt * 16 + g;
                af[mt][0] = __float_as_uint(as[(rr)     * AS_STRIDE + ks * 8 + t]);
                af[mt][1] = __float_as_uint(as[(rr + 8) * AS_STRIDE + ks * 8 + t]);
                af[mt][2] = __float_as_uint(as[(rr)     * AS_STRIDE + ks * 8 + t + 4]);
                af[mt][3] = __float_as_uint(as[(rr + 8) * AS_STRIDE + ks * 8 + t + 4]);
            }
#pragma unroll
            for (int nt = 0; nt < 4; nt++) {
                int cb = wn + nt * 8 + g;
                bf[nt][0] = __float_as_uint(bs[(ks * 8 + t)     * BS_STRIDE + cb]);
                bf[nt][1] = __float_as_uint(bs[(ks * 8 + t + 4) * BS_STRIDE + cb]);
            }
#pragma unroll
            for (int mt = 0; mt < 4; mt++)
#pragma unroll
                for (int nt = 0; nt < 4; nt++)
                    mma_tf32(acc[mt][nt], af[mt], bf[nt]);
        }
    }

    // epilogue
#pragma unroll
    for (int mt = 0; mt < 4; mt++) {
#pragma unroll
        for (int nt = 0; nt < 4; nt++) {
            int row = bm + wm + mt * 16 + g;
            int col = bn + wn + nt * 8 + t * 2;
            float v0 = acc[mt][nt][0], v1 = acc[mt][nt][1];
            float v2 = acc[mt][nt][2], v3 = acc[mt][nt][3];
            if (act == 1) {
                v0 = v0 / (1.f + expf(-v0));
                v1 = v1 / (1.f + expf(-v1));
                v2 = v2 / (1.f + expf(-v2));
                v3 = v3 / (1.f + expf(-v3));
            }
            *(float2*)&Cout[(size_t)row * C_ + col]       = make_float2(v0, v1);
            *(float2*)&Cout[(size_t)(row + 8) * C_ + col] = make_float2(v2, v3);
        }
    }
}

// ---------------- WKV5 recurrence + fused /8, groupnorm, *g -----------------
// 2 heads per CTA (512 threads), 128 CTAs = single balanced wave.
// Per head: 256 threads = (ig 0..3) x (j 0..63); thread owns S[i,j], i in
// [ig*16, ig*16+16). Next-step r/k/v/g prefetched into regs during compute.
__global__ __launch_bounds__(512) void wkv_kernel(
        const float* __restrict__ r, const float* __restrict__ k,
        const float* __restrict__ v, const float* __restrict__ g,
        const float* __restrict__ decay, const float* __restrict__ faaaa,
        const float* __restrict__ lnw, const float* __restrict__ lnb,
        float* __restrict__ yng) {
    __shared__ float sr[2][64], sk[2][64], sv[2][64], sruk[2][64];
    __shared__ float syp[2][256];
    __shared__ float sred[2][4];

    const int tid = threadIdx.x;
    const int hh  = tid >> 8;       // head slot within CTA
    const int lt  = tid & 255;
    const int bh  = blockIdx.x * 2 + hh;
    const int b = bh / H_, h = bh % H_;
    const int ig = lt >> 6;
    const int j  = lt & 63;

    float S[16], w16[16];
#pragma unroll
    for (int ii = 0; ii < 16; ii++) {
        S[ii] = 0.f;
        w16[ii] = expf(-expf(decay[h * 64 + ig * 16 + ii]));
    }
    float uu = 0.f;
    if (lt >= 192) uu = faaaa[h * 64 + (lt - 192)];
    float lw = 1.f, lb = 0.f;
    if (lt < 64) { lw = lnw[h * 64 + lt]; lb = lnb[h * 64 + lt]; }

    size_t base = (size_t)b * T_ * C_ + (size_t)h * 64;
    const float inv_div = 1.f / 8.f;

    // initial prefetch (t = 0)
    float pa = 0.f, pb = 0.f, pg = 0.f;
    if (lt < 64)       { pa = r[base + lt]; pg = g[base + lt]; }
    else if (lt < 128)   pa = k[base + (lt - 64)];
    else if (lt < 192)   pa = v[base + (lt - 128)];
    else               { pa = r[base + (lt - 192)]; pb = k[base + (lt - 192)]; }

    for (int t = 0; t < T_; t++) {
        // publish prefetched values for step t
        if (lt < 64)       sr[hh][lt]       = pa;
        else if (lt < 128) sk[hh][lt - 64]  = pa;
        else if (lt < 192) sv[hh][lt - 128] = pa;
        else               sruk[hh][lt - 192] = pa * uu * pb;
        const float gcur = pg;
        __syncthreads();

        // prefetch step t+1 (overlaps with compute below)
        if (t + 1 < T_) {
            size_t nb = base + C_;
            if (lt < 64)       { pa = r[nb + lt]; pg = g[nb + lt]; }
            else if (lt < 128)   pa = k[nb + (lt - 64)];
            else if (lt < 192)   pa = v[nb + (lt - 128)];
            else               { pa = r[nb + (lt - 192)]; pb = k[nb + (lt - 192)]; }
        }

        const float vj = sv[hh][j];
        float yp = 0.f, cp = 0.f;
#pragma unroll
        for (int ii = 0; ii < 16; ii++) {
            float ri = sr[hh][ig * 16 + ii];
            float ki = sk[hh][ig * 16 + ii];
            yp = fmaf(ri, S[ii], yp);             // uses S BEFORE update
            S[ii] = fmaf(w16[ii], S[ii], ki * vj);
            cp += sruk[hh][ig * 16 + ii];
        }
        yp = fmaf(cp, vj, yp);
        syp[hh][ig * 64 + j] = yp;
        __syncthreads();

        float yh = 0.f;
        if (lt < 64) {
            float y = syp[hh][j] + syp[hh][64 + j] + syp[hh][128 + j] + syp[hh][192 + j];
            yh = y * inv_div;
            float s1 = yh, s2 = yh * yh;
#pragma unroll
            for (int off = 16; off; off >>= 1) {
                s1 += __shfl_xor_sync(0xffffffffu, s1, off);
                s2 += __shfl_xor_sync(0xffffffffu, s2, off);
            }
            if ((lt & 31) == 0) {
                sred[hh][(lt >> 5) * 2]     = s1;
                sred[hh][(lt >> 5) * 2 + 1] = s2;
            }
        }
        __syncthreads();
        if (lt < 64) {
            float m1 = (sred[hh][0] + sred[hh][2]) * (1.f / 64.f);
            float m2 = (sred[hh][1] + sred[hh][3]) * (1.f / 64.f);
            float var = m2 - m1 * m1;
            float yn = (yh - m1) * rsqrtf(var + 1e-5f) * lw + lb;
            float o  = yn * gcur;
            yng[base + lt] = to_tf32(o);          // pre-round for Wo GEMM
        }
        base += C_;
    }
}

// ---------------- host launch ----------------
extern "C" void kernel_launch(void* const* d_in, const int* in_sizes, int n_in,
                              void* d_out, int out_size) {
    const float* x     = (const float*)d_in[0];
    const float* tmk   = (const float*)d_in[1];
    const float* tmv   = (const float*)d_in[2];
    const float* tmr   = (const float*)d_in[3];
    const float* tmg   = (const float*)d_in[4];
    const float* decay = (const float*)d_in[5];
    const float* faaaa = (const float*)d_in[6];
    const float* Wr    = (const float*)d_in[7];
    const float* Wk    = (const float*)d_in[8];
    const float* Wv    = (const float*)d_in[9];
    const float* Wg    = (const float*)d_in[10];
    const float* Wo    = (const float*)d_in[11];
    const float* lnw   = (const float*)d_in[12];
    const float* lnb   = (const float*)d_in[13];

    float *xk, *xv, *xr, *xg, *rr, *kk, *vv, *gg, *yng, *Wbuf;
    cudaGetSymbolAddress((void**)&xk,  g_xk);
    cudaGetSymbolAddress((void**)&xv,  g_xv);
    cudaGetSymbolAddress((void**)&xr,  g_xr);
    cudaGetSymbolAddress((void**)&xg,  g_xg);
    cudaGetSymbolAddress((void**)&rr,  g_r);
    cudaGetSymbolAddress((void**)&kk,  g_k);
    cudaGetSymbolAddress((void**)&vv,  g_v);
    cudaGetSymbolAddress((void**)&gg,  g_g);
    cudaGetSymbolAddress((void**)&yng, g_yng);
    cudaGetSymbolAddress((void**)&Wbuf, g_W);
    float* w0 = Wbuf + 0 * (size_t)CC_;
    float* w1 = Wbuf + 1 * (size_t)CC_;
    float* w2 = Wbuf + 2 * (size_t)CC_;
    float* w3 = Wbuf + 3 * (size_t)CC_;
    float* w4 = Wbuf + 4 * (size_t)CC_;

    // opt-in smem for the pipelined GEMM (executes immediately; not captured)
    cudaFuncSetAttribute(gemm_tf32_kernel,
                         cudaFuncAttributeMaxDynamicSharedMemorySize, GEMM_SMEM);

    // 1) round weights to tf32 bit patterns (layout [K,N] unchanged)
    {
        int n4 = CC_ / 4;
        int grid = (n4 + 255) / 256;
        round_tf32_kernel<<<grid, 256>>>((const float4*)Wr, (float4*)w0, n4);
        round_tf32_kernel<<<grid, 256>>>((const float4*)Wk, (float4*)w1, n4);
        round_tf32_kernel<<<grid, 256>>>((const float4*)Wv, (float4*)w2, n4);
        round_tf32_kernel<<<grid, 256>>>((const float4*)Wg, (float4*)w3, n4);
        round_tf32_kernel<<<grid, 256>>>((const float4*)Wo, (float4*)w4, n4);
    }

    // 2) token-shift mixes (tf32-rounded)
    {
        int n4 = BT_ * (C_ / 4);
        int grid = (n4 + 255) / 256;
        mix_kernel<<<grid, 256>>>((const float4*)x,
                                  (const float4*)tmk, (const float4*)tmv,
                                  (const float4*)tmr, (const float4*)tmg,
                                  (float4*)xk, (float4*)xv,
                                  (float4*)xr, (float4*)xg);
    }

    // 3) projections: r,k,v plain; g with silu
    dim3 gemm_grid(C_ / GBN, BT_ / GBM);   // (16, 128)
    gemm_tf32_kernel<<<gemm_grid, 256, GEMM_SMEM>>>(xr, w0, rr, 0);
    gemm_tf32_kernel<<<gemm_grid, 256, GEMM_SMEM>>>(xk, w1, kk, 0);
    gemm_tf32_kernel<<<gemm_grid, 256, GEMM_SMEM>>>(xv, w2, vv, 0);
    gemm_tf32_kernel<<<gemm_grid, 256, GEMM_SMEM>>>(xg, w3, gg, 1);

    // 4) WKV recurrence + fused /8 + groupnorm + *g  -> yng (tf32-rounded)
    wkv_kernel<<<B_ * H_ / 2, 512>>>(rr, kk, vv, gg, decay, faaaa, lnw, lnb, yng);

    // 5) output projection
    gemm_tf32_kernel<<<gemm_grid, 256, GEMM_SMEM>>>(yng, w4, (float*)d_out, 0);
}

// round 7
// speedup vs baseline: 2.0583x; 1.0087x over previous
#include <cuda_runtime.h>
#include <cstdint>
#include <cstddef>

// ---------------- problem constants ----------------
#define B_   8
#define T_   2048
#define C_   2048
#define H_   32
#define HS_  64
#define BT_  (B_*T_)          // 16384
#define CC_  (C_*C_)          // 4194304

// ---------------- scratch (device globals; no allocation) ----------------
__device__ float g_xk[BT_*(size_t)C_];
__device__ float g_xv[BT_*(size_t)C_];
__device__ float g_xr[BT_*(size_t)C_];
__device__ float g_xg[BT_*(size_t)C_];
__device__ float g_r [BT_*(size_t)C_];
__device__ float g_k [BT_*(size_t)C_];
__device__ float g_v [BT_*(size_t)C_];
__device__ float g_g [BT_*(size_t)C_];
__device__ float g_yng[BT_*(size_t)C_];
__device__ float g_W[5][CC_];   // tf32-rounded Wr,Wk,Wv,Wg,Wo  (layout [K,N])

// ---------------- helpers ----------------
__device__ __forceinline__ float to_tf32(float x) {
    uint32_t o;
    asm("cvt.rna.tf32.f32 %0, %1;" : "=r"(o) : "f"(x));
    return __uint_as_float(o);
}

__device__ __forceinline__ uint32_t smem_u32(const void* p) {
    return (uint32_t)__cvta_generic_to_shared(p);
}

__device__ __forceinline__ void mma_tf32(float (&c)[4],
                                         const uint32_t (&a)[4],
                                         const uint32_t (&b)[2]) {
    asm volatile(
        "mma.sync.aligned.m16n8k8.row.col.f32.tf32.tf32.f32 "
        "{%0,%1,%2,%3}, {%4,%5,%6,%7}, {%8,%9}, {%0,%1,%2,%3};\n"
        : "+f"(c[0]), "+f"(c[1]), "+f"(c[2]), "+f"(c[3])
        : "r"(a[0]), "r"(a[1]), "r"(a[2]), "r"(a[3]),
          "r"(b[0]), "r"(b[1]));
}

// ---------------- weight rounding (fp32 -> tf32 bits) ----------------
__global__ void round_tf32_kernel(const float4* __restrict__ src,
                                  float4* __restrict__ dst, int n4) {
    int i = blockIdx.x * blockDim.x + threadIdx.x;
    if (i >= n4) return;
    float4 v = src[i];
    v.x = to_tf32(v.x); v.y = to_tf32(v.y);
    v.z = to_tf32(v.z); v.w = to_tf32(v.w);
    dst[i] = v;
}

// ---------------- token-shift mix: xk/xv/xr/xg (tf32-rounded) ----------------
__global__ void mix_kernel(const float4* __restrict__ x,
                           const float4* __restrict__ tmk,
                           const float4* __restrict__ tmv,
                           const float4* __restrict__ tmr,
                           const float4* __restrict__ tmg,
                           float4* __restrict__ xk, float4* __restrict__ xv,
                           float4* __restrict__ xr, float4* __restrict__ xg) {
    const int C4 = C_ / 4;
    int idx = blockIdx.x * blockDim.x + threadIdx.x;
    if (idx >= BT_ * C4) return;
    int c4 = idx % C4;
    int bt = idx / C4;
    int t  = bt % T_;
    float4 xc = x[idx];
    float4 xp = make_float4(0.f, 0.f, 0.f, 0.f);
    if (t != 0) xp = x[idx - C4];
    float4 mk = tmk[c4], mv = tmv[c4], mr = tmr[c4], mg = tmg[c4];
    float4 o;
#define MIXC(dst, m) \
    o.x = to_tf32(fmaf(m.x, xc.x - xp.x, xp.x)); \
    o.y = to_tf32(fmaf(m.y, xc.y - xp.y, xp.y)); \
    o.z = to_tf32(fmaf(m.z, xc.z - xp.z, xp.z)); \
    o.w = to_tf32(fmaf(m.w, xc.w - xp.w, xp.w)); \
    dst[idx] = o;
    MIXC(xk, mk)
    MIXC(xv, mv)
    MIXC(xr, mr)
    MIXC(xg, mg)
#undef MIXC
}

// ---------------- tf32 mma.sync GEMM, warp tile 64x64 ------------------------
// C[M=16384, N=2048] = A[M,K=2048] @ B[K,N]      (B row-major [K,N])
// BM=BN=128, BK=32, 3 stages, 128 threads (4 warps 2x2), warp tile 64x64.
// A smem: [128][36] floats (stride 36: banks 4g+t, conflict-free)
// B smem: [32][136] floats (stride 136: banks 8t+g, conflict-free)
#define GBM   128
#define GBN   128
#define GBK   32
#define NSTG  3
#define NTIL  (C_ / GBK)          // 64
#define AS_STRIDE 36
#define BS_STRIDE 136
#define AS_FLOATS (GBM * AS_STRIDE)            // 4608
#define BS_FLOATS (GBK * BS_STRIDE)            // 4352
#define STG_FLOATS (AS_FLOATS + BS_FLOATS)     // 8960
#define GEMM_SMEM (NSTG * STG_FLOATS * 4)      // 107520 bytes

__global__ __launch_bounds__(128, 2) void gemm_tf32_kernel(
        const float* __restrict__ Ag, const float* __restrict__ Bw,
        float* __restrict__ Cout, int act) {
    extern __shared__ float sm[];
    const uint32_t smb = smem_u32(sm);

    const int tid  = threadIdx.x;
    const int lane = tid & 31;
    const int warp = tid >> 5;
    const int wm = (warp >> 1) * 64;   // 0 or 64
    const int wn = (warp & 1) * 64;    // 0 or 64
    const int bm = blockIdx.y * GBM;
    const int bn = blockIdx.x * GBN;
    const int g  = lane >> 2;      // 0..7
    const int t  = lane & 3;       // 0..3

    float acc[4][8][4];
#pragma unroll
    for (int i = 0; i < 4; i++)
#pragma unroll
        for (int j = 0; j < 8; j++)
#pragma unroll
            for (int q = 0; q < 4; q++) acc[i][j][q] = 0.f;

    auto issue_tile = [&](int kt) {
        const int s = kt % NSTG;
        const uint32_t sA = smb + (uint32_t)(s * STG_FLOATS) * 4u;
        const uint32_t sB = sA + AS_FLOATS * 4u;
#pragma unroll
        for (int q = 0; q < 8; q++) {
            int idx = tid + q * 128;
            int r  = idx >> 3;                // 0..127
            int k4 = idx & 7;                 // 0..7
            const float* gp = Ag + (size_t)(bm + r) * C_ + kt * GBK + k4 * 4;
            uint32_t so = sA + (uint32_t)(r * AS_STRIDE + k4 * 4) * 4u;
            asm volatile("cp.async.cg.shared.global [%0], [%1], 16;"
                         :: "r"(so), "l"(gp) : "memory");
        }
#pragma unroll
        for (int q = 0; q < 8; q++) {
            int idx = tid + q * 128;
            int kr = idx >> 5;                // 0..31
            int n4 = idx & 31;                // 0..31
            const float* gp = Bw + (size_t)(kt * GBK + kr) * C_ + bn + n4 * 4;
            uint32_t so = sB + (uint32_t)(kr * BS_STRIDE + n4 * 4) * 4u;
            asm volatile("cp.async.cg.shared.global [%0], [%1], 16;"
                         :: "r"(so), "l"(gp) : "memory");
        }
        asm volatile("cp.async.commit_group;" ::: "memory");
    };

    // prologue: 2 stages in flight
    issue_tile(0);
    issue_tile(1);

#pragma unroll 1
    for (int kt = 0; kt < NTIL; kt++) {
        if (kt + NSTG - 1 < NTIL) {
            asm volatile("cp.async.wait_group %0;" :: "n"(NSTG - 2) : "memory");
        } else {
            asm volatile("cp.async.wait_group 0;" ::: "memory");
        }
        __syncthreads();
        if (kt + NSTG - 1 < NTIL) issue_tile(kt + NSTG - 1);

        const int s = kt % NSTG;
        const float* as = sm + s * STG_FLOATS;
        const float* bs = as + AS_FLOATS;

#pragma unroll
        for (int ks = 0; ks < 4; ks++) {
            uint32_t af[4][4], bf[8][2];
#pragma unroll
            for (int mt = 0; mt < 4; mt++) {
                int rr = wm + mt * 16 + g;
                af[mt][0] = __float_as_uint(as[(rr)     * AS_STRIDE + ks * 8 + t]);
                af[mt][1] = __float_as_uint(as[(rr + 8) * AS_STRIDE + ks * 8 + t]);
                af[mt][2] = __float_as_uint(as[(rr)     * AS_STRIDE + ks * 8 + t + 4]);
                af[mt][3] = __float_as_uint(as[(rr + 8) * AS_STRIDE + ks * 8 + t + 4]);
            }
#pragma unroll
            for (int nt = 0; nt < 8; nt++) {
                int cb = wn + nt * 8 + g;
                bf[nt][0] = __float_as_uint(bs[(ks * 8 + t)     * BS_STRIDE + cb]);
                bf[nt][1] = __float_as_uint(bs[(ks * 8 + t + 4) * BS_STRIDE + cb]);
            }
#pragma unroll
            for (int mt = 0; mt < 4; mt++)
#pragma unroll
                for (int nt = 0; nt < 8; nt++)
                    mma_tf32(acc[mt][nt], af[mt], bf[nt]);
        }
    }

    // epilogue
#pragma unroll
    for (int mt = 0; mt < 4; mt++) {
#pragma unroll
        for (int nt = 0; nt < 8; nt++) {
            int row = bm + wm + mt * 16 + g;
            int col = bn + wn + nt * 8 + t * 2;
            float v0 = acc[mt][nt][0], v1 = acc[mt][nt][1];
            float v2 = acc[mt][nt][2], v3 = acc[mt][nt][3];
            if (act == 1) {
                v0 = v0 / (1.f + expf(-v0));
                v1 = v1 / (1.f + expf(-v1));
                v2 = v2 / (1.f + expf(-v2));
                v3 = v3 / (1.f + expf(-v3));
            }
            *(float2*)&Cout[(size_t)row * C_ + col]       = make_float2(v0, v1);
            *(float2*)&Cout[(size_t)(row + 8) * C_ + col] = make_float2(v2, v3);
        }
    }
}

// ---------------- WKV5 recurrence + fused /8, groupnorm, *g -----------------
// 2 heads per CTA (512 threads), 128 CTAs = single balanced wave.
// Per head: 256 threads = (ig 0..3) x (j 0..63); thread owns S[i,j], i in
// [ig*16, ig*16+16). y_j = r.S_:j + (sum_i r_i u_i k_i) * v_j ; the scalar
// ruk term is reduced once per step by warps 6..7 of each head (shuffle) and
// applied in the final groupnorm stage (NOT inside the 16-deep inner loop).
__global__ __launch_bounds__(512) void wkv_kernel(
        const float* __restrict__ r, const float* __restrict__ k,
        const float* __restrict__ v, const float* __restrict__ g,
        const float* __restrict__ decay, const float* __restrict__ faaaa,
        const float* __restrict__ lnw, const float* __restrict__ lnb,
        float* __restrict__ yng) {
    __shared__ __align__(16) float sr[2][64];
    __shared__ __align__(16) float sk[2][64];
    __shared__ float sv[2][64];
    __shared__ float syp[2][256];
    __shared__ float sred[2][4];
    __shared__ float sruk[2][2];

    const int tid = threadIdx.x;
    const int hh  = tid >> 8;       // head slot within CTA
    const int lt  = tid & 255;
    const int bh  = blockIdx.x * 2 + hh;
    const int b = bh / H_, h = bh % H_;
    const int ig = lt >> 6;
    const int j  = lt & 63;

    float S[16], w16[16];
#pragma unroll
    for (int ii = 0; ii < 16; ii++) {
        S[ii] = 0.f;
        w16[ii] = expf(-expf(decay[h * 64 + ig * 16 + ii]));
    }
    float uu = 0.f;
    if (lt >= 192) uu = faaaa[h * 64 + (lt - 192)];
    float lw = 1.f, lb = 0.f;
    if (lt < 64) { lw = lnw[h * 64 + lt]; lb = lnb[h * 64 + lt]; }

    size_t base = (size_t)b * T_ * C_ + (size_t)h * 64;
    const float inv_div = 1.f / 8.f;

    // initial prefetch (t = 0)
    float pa = 0.f, pb = 0.f, pg = 0.f;
    if (lt < 64)       { pa = r[base + lt]; pg = g[base + lt]; }
    else if (lt < 128)   pa = k[base + (lt - 64)];
    else if (lt < 192)   pa = v[base + (lt - 128)];
    else               { pa = r[base + (lt - 192)]; pb = k[base + (lt - 192)]; }

    for (int t = 0; t < T_; t++) {
        // publish prefetched values for step t; warps 6,7 reduce ruk scalar
        if (lt < 64)       sr[hh][lt]       = pa;
        else if (lt < 128) sk[hh][lt - 64]  = pa;
        else if (lt < 192) sv[hh][lt - 128] = pa;
        else {
            float val = pa * uu * pb;
#pragma unroll
            for (int off = 16; off; off >>= 1)
                val += __shfl_xor_sync(0xffffffffu, val, off);
            if ((lt & 31) == 0) sruk[hh][(lt >> 5) & 1] = val;
        }
        const float gcur = pg;
        __syncthreads();

        // prefetch step t+1 (overlaps with compute below)
        if (t + 1 < T_) {
            size_t nb = base + C_;
            if (lt < 64)       { pa = r[nb + lt]; pg = g[nb + lt]; }
            else if (lt < 128)   pa = k[nb + (lt - 64)];
            else if (lt < 192)   pa = v[nb + (lt - 128)];
            else               { pa = r[nb + (lt - 192)]; pb = k[nb + (lt - 192)]; }
        }

        const float vj = sv[hh][j];
        const float4* r4 = (const float4*)&sr[hh][ig * 16];
        const float4* k4 = (const float4*)&sk[hh][ig * 16];
        float yp = 0.f;
#pragma unroll
        for (int q = 0; q < 4; q++) {
            float4 rv = r4[q];
            float4 kv = k4[q];
            yp = fmaf(rv.x, S[q*4+0], yp);
            S[q*4+0] = fmaf(w16[q*4+0], S[q*4+0], kv.x * vj);
            yp = fmaf(rv.y, S[q*4+1], yp);
            S[q*4+1] = fmaf(w16[q*4+1], S[q*4+1], kv.y * vj);
            yp = fmaf(rv.z, S[q*4+2], yp);
            S[q*4+2] = fmaf(w16[q*4+2], S[q*4+2], kv.z * vj);
            yp = fmaf(rv.w, S[q*4+3], yp);
            S[q*4+3] = fmaf(w16[q*4+3], S[q*4+3], kv.w * vj);
        }
        syp[hh][ig * 64 + j] = yp;
        __syncthreads();

        float yh = 0.f;
        if (lt < 64) {
            float ruk = sruk[hh][0] + sruk[hh][1];
            float y = syp[hh][j] + syp[hh][64 + j] + syp[hh][128 + j]
                    + syp[hh][192 + j] + ruk * sv[hh][j];
            yh = y * inv_div;
            float s1 = yh, s2 = yh * yh;
#pragma unroll
            for (int off = 16; off; off >>= 1) {
                s1 += __shfl_xor_sync(0xffffffffu, s1, off);
                s2 += __shfl_xor_sync(0xffffffffu, s2, off);
            }
            if ((lt & 31) == 0) {
                sred[hh][(lt >> 5) * 2]     = s1;
                sred[hh][(lt >> 5) * 2 + 1] = s2;
            }
        }
        __syncthreads();
        if (lt < 64) {
            float m1 = (sred[hh][0] + sred[hh][2]) * (1.f / 64.f);
            float m2 = (sred[hh][1] + sred[hh][3]) * (1.f / 64.f);
            float var = m2 - m1 * m1;
            float yn = (yh - m1) * rsqrtf(var + 1e-5f) * lw + lb;
            float o  = yn * gcur;
            yng[base + lt] = to_tf32(o);          // pre-round for Wo GEMM
        }
        base += C_;
    }
}

// ---------------- host launch ----------------
extern "C" void kernel_launch(void* const* d_in, const int* in_sizes, int n_in,
                              void* d_out, int out_size) {
    const float* x     = (const float*)d_in[0];
    const float* tmk   = (const float*)d_in[1];
    const float* tmv   = (const float*)d_in[2];
    const float* tmr   = (const float*)d_in[3];
    const float* tmg   = (const float*)d_in[4];
    const float* decay = (const float*)d_in[5];
    const float* faaaa = (const float*)d_in[6];
    const float* Wr    = (const float*)d_in[7];
    const float* Wk    = (const float*)d_in[8];
    const float* Wv    = (const float*)d_in[9];
    const float* Wg    = (const float*)d_in[10];
    const float* Wo    = (const float*)d_in[11];
    const float* lnw   = (const float*)d_in[12];
    const float* lnb   = (const float*)d_in[13];

    float *xk, *xv, *xr, *xg, *rr, *kk, *vv, *gg, *yng, *Wbuf;
    cudaGetSymbolAddress((void**)&xk,  g_xk);
    cudaGetSymbolAddress((void**)&xv,  g_xv);
    cudaGetSymbolAddress((void**)&xr,  g_xr);
    cudaGetSymbolAddress((void**)&xg,  g_xg);
    cudaGetSymbolAddress((void**)&rr,  g_r);
    cudaGetSymbolAddress((void**)&kk,  g_k);
    cudaGetSymbolAddress((void**)&vv,  g_v);
    cudaGetSymbolAddress((void**)&gg,  g_g);
    cudaGetSymbolAddress((void**)&yng, g_yng);
    cudaGetSymbolAddress((void**)&Wbuf, g_W);
    float* w0 = Wbuf + 0 * (size_t)CC_;
    float* w1 = Wbuf + 1 * (size_t)CC_;
    float* w2 = Wbuf + 2 * (size_t)CC_;
    float* w3 = Wbuf + 3 * (size_t)CC_;
    float* w4 = Wbuf + 4 * (size_t)CC_;

    // opt-in smem for the pipelined GEMM (executes immediately; not captured)
    cudaFuncSetAttribute(gemm_tf32_kernel,
                         cudaFuncAttributeMaxDynamicSharedMemorySize, GEMM_SMEM);

    // 1) round weights to tf32 bit patterns (layout [K,N] unchanged)
    {
        int n4 = CC_ / 4;
        int grid = (n4 + 255) / 256;
        round_tf32_kernel<<<grid, 256>>>((const float4*)Wr, (float4*)w0, n4);
        round_tf32_kernel<<<grid, 256>>>((const float4*)Wk, (float4*)w1, n4);
        round_tf32_kernel<<<grid, 256>>>((const float4*)Wv, (float4*)w2, n4);
        round_tf32_kernel<<<grid, 256>>>((const float4*)Wg, (float4*)w3, n4);
        round_tf32_kernel<<<grid, 256>>>((const float4*)Wo, (float4*)w4, n4);
    }

    // 2) token-shift mixes (tf32-rounded)
    {
        int n4 = BT_ * (C_ / 4);
        int grid = (n4 + 255) / 256;
        mix_kernel<<<grid, 256>>>((const float4*)x,
                                  (const float4*)tmk, (const float4*)tmv,
                                  (const float4*)tmr, (const float4*)tmg,
                                  (float4*)xk, (float4*)xv,
                                  (float4*)xr, (float4*)xg);
    }

    // 3) projections: r,k,v plain; g with silu
    dim3 gemm_grid(C_ / GBN, BT_ / GBM);   // (16, 128)
    gemm_tf32_kernel<<<gemm_grid, 128, GEMM_SMEM>>>(xr, w0, rr, 0);
    gemm_tf32_kernel<<<gemm_grid, 128, GEMM_SMEM>>>(xk, w1, kk, 0);
    gemm_tf32_kernel<<<gemm_grid, 128, GEMM_SMEM>>>(xv, w2, vv, 0);
    gemm_tf32_kernel<<<gemm_grid, 128, GEMM_SMEM>>>(xg, w3, gg, 1);

    // 4) WKV recurrence + fused /8 + groupnorm + *g  -> yng (tf32-rounded)
    wkv_kernel<<<B_ * H_ / 2, 512>>>(rr, kk, vv, gg, decay, faaaa, lnw, lnb, yng);

    // 5) output projection
    gemm_tf32_kernel<<<gemm_grid, 128, GEMM_SMEM>>>(yng, w4, (float*)d_out, 0);
}

// round 8
// speedup vs baseline: 2.0697x; 1.0055x over previous
#include <cuda_runtime.h>
#include <cstdint>
#include <cstddef>

// ---------------- problem constants ----------------
#define B_   8
#define T_   2048
#define C_   2048
#define H_   32
#define HS_  64
#define BT_  (B_*T_)          // 16384
#define CC_  (C_*C_)          // 4194304

// ---------------- scratch (device globals; no allocation) ----------------
__device__ float g_xk[BT_*(size_t)C_];
__device__ float g_xv[BT_*(size_t)C_];
__device__ float g_xr[BT_*(size_t)C_];
__device__ float g_xg[BT_*(size_t)C_];
__device__ float g_r [BT_*(size_t)C_];
__device__ float g_k [BT_*(size_t)C_];
__device__ float g_v [BT_*(size_t)C_];
__device__ float g_g [BT_*(size_t)C_];
__device__ float g_yng[BT_*(size_t)C_];
__device__ float g_W[5][CC_];   // tf32-rounded Wr,Wk,Wv,Wg,Wo  (layout [K,N])

// ---------------- helpers ----------------
__device__ __forceinline__ float to_tf32(float x) {
    uint32_t o;
    asm("cvt.rna.tf32.f32 %0, %1;" : "=r"(o) : "f"(x));
    return __uint_as_float(o);
}

__device__ __forceinline__ uint32_t smem_u32(const void* p) {
    return (uint32_t)__cvta_generic_to_shared(p);
}

__device__ __forceinline__ void mma_tf32(float (&c)[4],
                                         const uint32_t (&a)[4],
                                         const uint32_t (&b)[2]) {
    asm volatile(
        "mma.sync.aligned.m16n8k8.row.col.f32.tf32.tf32.f32 "
        "{%0,%1,%2,%3}, {%4,%5,%6,%7}, {%8,%9}, {%0,%1,%2,%3};\n"
        : "+f"(c[0]), "+f"(c[1]), "+f"(c[2]), "+f"(c[3])
        : "r"(a[0]), "r"(a[1]), "r"(a[2]), "r"(a[3]),
          "r"(b[0]), "r"(b[1]));
}

// ---------------- weight rounding (fp32 -> tf32 bits) ----------------
__global__ void round_tf32_kernel(const float4* __restrict__ src,
                                  float4* __restrict__ dst, int n4) {
    int i = blockIdx.x * blockDim.x + threadIdx.x;
    if (i >= n4) return;
    float4 v = src[i];
    v.x = to_tf32(v.x); v.y = to_tf32(v.y);
    v.z = to_tf32(v.z); v.w = to_tf32(v.w);
    dst[i] = v;
}

// ---------------- token-shift mix: xk/xv/xr/xg (tf32-rounded) ----------------
__global__ void mix_kernel(const float4* __restrict__ x,
                           const float4* __restrict__ tmk,
                           const float4* __restrict__ tmv,
                           const float4* __restrict__ tmr,
                           const float4* __restrict__ tmg,
                           float4* __restrict__ xk, float4* __restrict__ xv,
                           float4* __restrict__ xr, float4* __restrict__ xg) {
    const int C4 = C_ / 4;
    int idx = blockIdx.x * blockDim.x + threadIdx.x;
    if (idx >= BT_ * C4) return;
    int c4 = idx % C4;
    int bt = idx / C4;
    int t  = bt % T_;
    float4 xc = x[idx];
    float4 xp = make_float4(0.f, 0.f, 0.f, 0.f);
    if (t != 0) xp = x[idx - C4];
    float4 mk = tmk[c4], mv = tmv[c4], mr = tmr[c4], mg = tmg[c4];
    float4 o;
#define MIXC(dst, m) \
    o.x = to_tf32(fmaf(m.x, xc.x - xp.x, xp.x)); \
    o.y = to_tf32(fmaf(m.y, xc.y - xp.y, xp.y)); \
    o.z = to_tf32(fmaf(m.z, xc.z - xp.z, xp.z)); \
    o.w = to_tf32(fmaf(m.w, xc.w - xp.w, xp.w)); \
    dst[idx] = o;
    MIXC(xk, mk)
    MIXC(xv, mv)
    MIXC(xr, mr)
    MIXC(xg, mg)
#undef MIXC
}

// ---------------- tf32 mma.sync GEMM, warp tile 64x64 ------------------------
// C[M=16384, N=2048] = A[M,K=2048] @ B[K,N]      (B row-major [K,N])
// BM=BN=128, BK=32, 3 stages, 128 threads (4 warps 2x2), warp tile 64x64.
// A smem: [128][36] floats (stride 36: banks 4g+t, conflict-free)
// B smem: [32][136] floats (stride 136: banks 8t+g, conflict-free)
#define GBM   128
#define GBN   128
#define GBK   32
#define NSTG  3
#define NTIL  (C_ / GBK)          // 64
#define AS_STRIDE 36
#define BS_STRIDE 136
#define AS_FLOATS (GBM * AS_STRIDE)            // 4608
#define BS_FLOATS (GBK * BS_STRIDE)            // 4352
#define STG_FLOATS (AS_FLOATS + BS_FLOATS)     // 8960
#define GEMM_SMEM (NSTG * STG_FLOATS * 4)      // 107520 bytes

__global__ __launch_bounds__(128, 2) void gemm_tf32_kernel(
        const float* __restrict__ Ag, const float* __restrict__ Bw,
        float* __restrict__ Cout, int act) {
    extern __shared__ float sm[];
    const uint32_t smb = smem_u32(sm);

    const int tid  = threadIdx.x;
    const int lane = tid & 31;
    const int warp = tid >> 5;
    const int wm = (warp >> 1) * 64;   // 0 or 64
    const int wn = (warp & 1) * 64;    // 0 or 64
    const int bm = blockIdx.y * GBM;
    const int bn = blockIdx.x * GBN;
    const int g  = lane >> 2;      // 0..7
    const int t  = lane & 3;       // 0..3

    float acc[4][8][4];
#pragma unroll
    for (int i = 0; i < 4; i++)
#pragma unroll
        for (int j = 0; j < 8; j++)
#pragma unroll
            for (int q = 0; q < 4; q++) acc[i][j][q] = 0.f;

    auto issue_tile = [&](int kt) {
        const int s = kt % NSTG;
        const uint32_t sA = smb + (uint32_t)(s * STG_FLOATS) * 4u;
        const uint32_t sB = sA + AS_FLOATS * 4u;
#pragma unroll
        for (int q = 0; q < 8; q++) {
            int idx = tid + q * 128;
            int r  = idx >> 3;                // 0..127
            int k4 = idx & 7;                 // 0..7
            const float* gp = Ag + (size_t)(bm + r) * C_ + kt * GBK + k4 * 4;
            uint32_t so = sA + (uint32_t)(r * AS_STRIDE + k4 * 4) * 4u;
            asm volatile("cp.async.cg.shared.global [%0], [%1], 16;"
                         :: "r"(so), "l"(gp) : "memory");
        }
#pragma unroll
        for (int q = 0; q < 8; q++) {
            int idx = tid + q * 128;
            int kr = idx >> 5;                // 0..31
            int n4 = idx & 31;                // 0..31
            const float* gp = Bw + (size_t)(kt * GBK + kr) * C_ + bn + n4 * 4;
            uint32_t so = sB + (uint32_t)(kr * BS_STRIDE + n4 * 4) * 4u;
            asm volatile("cp.async.cg.shared.global [%0], [%1], 16;"
                         :: "r"(so), "l"(gp) : "memory");
        }
        asm volatile("cp.async.commit_group;" ::: "memory");
    };

    // prologue: 2 stages in flight
    issue_tile(0);
    issue_tile(1);

#pragma unroll 1
    for (int kt = 0; kt < NTIL; kt++) {
        if (kt + NSTG - 1 < NTIL) {
            asm volatile("cp.async.wait_group %0;" :: "n"(NSTG - 2) : "memory");
        } else {
            asm volatile("cp.async.wait_group 0;" ::: "memory");
        }
        __syncthreads();
        if (kt + NSTG - 1 < NTIL) issue_tile(kt + NSTG - 1);

        const int s = kt % NSTG;
        const float* as = sm + s * STG_FLOATS;
        const float* bs = as + AS_FLOATS;

#pragma unroll
        for (int ks = 0; ks < 4; ks++) {
            uint32_t af[4][4], bf[8][2];
#pragma unroll
            for (int mt = 0; mt < 4; mt++) {
                int rr = wm + mt * 16 + g;
                af[mt][0] = __float_as_uint(as[(rr)     * AS_STRIDE + ks * 8 + t]);
                af[mt][1] = __float_as_uint(as[(rr + 8) * AS_STRIDE + ks * 8 + t]);
                af[mt][2] = __float_as_uint(as[(rr)     * AS_STRIDE + ks * 8 + t + 4]);
                af[mt][3] = __float_as_uint(as[(rr + 8) * AS_STRIDE + ks * 8 + t + 4]);
            }
#pragma unroll
            for (int nt = 0; nt < 8; nt++) {
                int cb = wn + nt * 8 + g;
                bf[nt][0] = __float_as_uint(bs[(ks * 8 + t)     * BS_STRIDE + cb]);
                bf[nt][1] = __float_as_uint(bs[(ks * 8 + t + 4) * BS_STRIDE + cb]);
            }
#pragma unroll
            for (int mt = 0; mt < 4; mt++)
#pragma unroll
                for (int nt = 0; nt < 8; nt++)
                    mma_tf32(acc[mt][nt], af[mt], bf[nt]);
        }
    }

    // epilogue
#pragma unroll
    for (int mt = 0; mt < 4; mt++) {
#pragma unroll
        for (int nt = 0; nt < 8; nt++) {
            int row = bm + wm + mt * 16 + g;
            int col = bn + wn + nt * 8 + t * 2;
            float v0 = acc[mt][nt][0], v1 = acc[mt][nt][1];
            float v2 = acc[mt][nt][2], v3 = acc[mt][nt][3];
            if (act == 1) {
                v0 = v0 / (1.f + expf(-v0));
                v1 = v1 / (1.f + expf(-v1));
                v2 = v2 / (1.f + expf(-v2));
                v3 = v3 / (1.f + expf(-v3));
            }
            *(float2*)&Cout[(size_t)row * C_ + col]       = make_float2(v0, v1);
            *(float2*)&Cout[(size_t)(row + 8) * C_ + col] = make_float2(v2, v3);
        }
    }
}

// ---------------- WKV5 recurrence + fused /8, groupnorm, *g -----------------
// 2 heads per CTA (512 threads), 128 CTAs = single balanced wave.
// Per head: 256 threads = (ig 0..3) x (j 0..63); thread owns S[i,j], i in
// [ig*16, ig*16+16). y_j = r.S_:j + (sum_i r_i u_i k_i) * v_j ; the scalar
// ruk term is reduced once per step by warps 6..7 of each head (shuffle) and
// applied in the final groupnorm stage (NOT inside the 16-deep inner loop).
__global__ __launch_bounds__(512) void wkv_kernel(
        const float* __restrict__ r, const float* __restrict__ k,
        const float* __restrict__ v, const float* __restrict__ g,
        const float* __restrict__ decay, const float* __restrict__ faaaa,
        const float* __restrict__ lnw, const float* __restrict__ lnb,
        float* __restrict__ yng) {
    __shared__ __align__(16) float sr[2][64];
    __shared__ __align__(16) float sk[2][64];
    __shared__ float sv[2][64];
    __shared__ float syp[2][256];
    __shared__ float sred[2][4];
    __shared__ float sruk[2][2];

    const int tid = threadIdx.x;
    const int hh  = tid >> 8;       // head slot within CTA
    const int lt  = tid & 255;
    const int bh  = blockIdx.x * 2 + hh;
    const int b = bh / H_, h = bh % H_;
    const int ig = lt >> 6;
    const int j  = lt & 63;

    float S[16], w16[16];
#pragma unroll
    for (int ii = 0; ii < 16; ii++) {
        S[ii] = 0.f;
        w16[ii] = expf(-expf(decay[h * 64 + ig * 16 + ii]));
    }
    float uu = 0.f;
    if (lt >= 192) uu = faaaa[h * 64 + (lt - 192)];
    float lw = 1.f, lb = 0.f;
    if (lt < 64) { lw = lnw[h * 64 + lt]; lb = lnb[h * 64 + lt]; }

    size_t base = (size_t)b * T_ * C_ + (size_t)h * 64;
    const float inv_div = 1.f / 8.f;

    // initial prefetch (t = 0)
    float pa = 0.f, pb = 0.f, pg = 0.f;
    if (lt < 64)       { pa = r[base + lt]; pg = g[base + lt]; }
    else if (lt < 128)   pa = k[base + (lt - 64)];
    else if (lt < 192)   pa = v[base + (lt - 128)];
    else               { pa = r[base + (lt - 192)]; pb = k[base + (lt - 192)]; }

    for (int t = 0; t < T_; t++) {
        // publish prefetched values for step t; warps 6,7 reduce ruk scalar
        if (lt < 64)       sr[hh][lt]       = pa;
        else if (lt < 128) sk[hh][lt - 64]  = pa;
        else if (lt < 192) sv[hh][lt - 128] = pa;
        else {
            float val = pa * uu * pb;
#pragma unroll
            for (int off = 16; off; off >>= 1)
                val += __shfl_xor_sync(0xffffffffu, val, off);
            if ((lt & 31) == 0) sruk[hh][(lt >> 5) & 1] = val;
        }
        const float gcur = pg;
        __syncthreads();

        // prefetch step t+1 (overlaps with compute below)
        if (t + 1 < T_) {
            size_t nb = base + C_;
            if (lt < 64)       { pa = r[nb + lt]; pg = g[nb + lt]; }
            else if (lt < 128)   pa = k[nb + (lt - 64)];
            else if (lt < 192)   pa = v[nb + (lt - 128)];
            else               { pa = r[nb + (lt - 192)]; pb = k[nb + (lt - 192)]; }
        }

        const float vj = sv[hh][j];
        const float4* r4 = (const float4*)&sr[hh][ig * 16];
        const float4* k4 = (const float4*)&sk[hh][ig * 16];
        float yp = 0.f;
#pragma unroll
        for (int q = 0; q < 4; q++) {
            float4 rv = r4[q];
            float4 kv = k4[q];
            yp = fmaf(rv.x, S[q*4+0], yp);
            S[q*4+0] = fmaf(w16[q*4+0], S[q*4+0], kv.x * vj);
            yp = fmaf(rv.y, S[q*4+1], yp);
            S[q*4+1] = fmaf(w16[q*4+1], S[q*4+1], kv.y * vj);
            yp = fmaf(rv.z, S[q*4+2], yp);
            S[q*4+2] = fmaf(w16[q*4+2], S[q*4+2], kv.z * vj);
            yp = fmaf(rv.w, S[q*4+3], yp);
            S[q*4+3] = fmaf(w16[q*4+3], S[q*4+3], kv.w * vj);
        }
        syp[hh][ig * 64 + j] = yp;
        __syncthreads();

        float yh = 0.f;
        if (lt < 64) {
            float ruk = sruk[hh][0] + sruk[hh][1];
            float y = syp[hh][j] + syp[hh][64 + j] + syp[hh][128 + j]
                    + syp[hh][192 + j] + ruk * sv[hh][j];
            yh = y * inv_div;
            float s1 = yh, s2 = yh * yh;
#pragma unroll
            for (int off = 16; off; off >>= 1) {
                s1 += __shfl_xor_sync(0xffffffffu, s1, off);
                s2 += __shfl_xor_sync(0xffffffffu, s2, off);
            }
            if ((lt & 31) == 0) {
                sred[hh][(lt >> 5) * 2]     = s1;
                sred[hh][(lt >> 5) * 2 + 1] = s2;
            }
        }
        __syncthreads();
        if (lt < 64) {
            float m1 = (sred[hh][0] + sred[hh][2]) * (1.f / 64.f);
            float m2 = (sred[hh][1] + sred[hh][3]) * (1.f / 64.f);
            float var = m2 - m1 * m1;
            float yn = (yh - m1) * rsqrtf(var + 1e-5f) * lw + lb;
            float o  = yn * gcur;
            yng[base + lt] = to_tf32(o);          // pre-round for Wo GEMM
        }
        base += C_;
    }
}

// ---------------- host launch ----------------
extern "C" void kernel_launch(void* const* d_in, const int* in_sizes, int n_in,
                              void* d_out, int out_size) {
    const float* x     = (const float*)d_in[0];
    const float* tmk   = (const float*)d_in[1];
    const float* tmv   = (const float*)d_in[2];
    const float* tmr   = (const float*)d_in[3];
    const float* tmg   = (const float*)d_in[4];
    const float* decay = (const float*)d_in[5];
    const float* faaaa = (const float*)d_in[6];
    const float* Wr    = (const float*)d_in[7];
    const float* Wk    = (const float*)d_in[8];
    const float* Wv    = (const float*)d_in[9];
    const float* Wg    = (const float*)d_in[10];
    const float* Wo    = (const float*)d_in[11];
    const float* lnw   = (const float*)d_in[12];
    const float* lnb   = (const float*)d_in[13];

    float *xk, *xv, *xr, *xg, *rr, *kk, *vv, *gg, *yng, *Wbuf;
    cudaGetSymbolAddress((void**)&xk,  g_xk);
    cudaGetSymbolAddress((void**)&xv,  g_xv);
    cudaGetSymbolAddress((void**)&xr,  g_xr);
    cudaGetSymbolAddress((void**)&xg,  g_xg);
    cudaGetSymbolAddress((void**)&rr,  g_r);
    cudaGetSymbolAddress((void**)&kk,  g_k);
    cudaGetSymbolAddress((void**)&vv,  g_v);
    cudaGetSymbolAddress((void**)&gg,  g_g);
    cudaGetSymbolAddress((void**)&yng, g_yng);
    cudaGetSymbolAddress((void**)&Wbuf, g_W);
    float* w0 = Wbuf + 0 * (size_t)CC_;
    float* w1 = Wbuf + 1 * (size_t)CC_;
    float* w2 = Wbuf + 2 * (size_t)CC_;
    float* w3 = Wbuf + 3 * (size_t)CC_;
    float* w4 = Wbuf + 4 * (size_t)CC_;

    // opt-in smem for the pipelined GEMM (executes immediately; not captured)
    cudaFuncSetAttribute(gemm_tf32_kernel,
                         cudaFuncAttributeMaxDynamicSharedMemorySize, GEMM_SMEM);

    // 1) round weights to tf32 bit patterns (layout [K,N] unchanged)
    {
        int n4 = CC_ / 4;
        int grid = (n4 + 255) / 256;
        round_tf32_kernel<<<grid, 256>>>((const float4*)Wr, (float4*)w0, n4);
        round_tf32_kernel<<<grid, 256>>>((const float4*)Wk, (float4*)w1, n4);
        round_tf32_kernel<<<grid, 256>>>((const float4*)Wv, (float4*)w2, n4);
        round_tf32_kernel<<<grid, 256>>>((const float4*)Wg, (float4*)w3, n4);
        round_tf32_kernel<<<grid, 256>>>((const float4*)Wo, (float4*)w4, n4);
    }

    // 2) token-shift mixes (tf32-rounded)
    {
        int n4 = BT_ * (C_ / 4);
        int grid = (n4 + 255) / 256;
        mix_kernel<<<grid, 256>>>((const float4*)x,
                                  (const float4*)tmk, (const float4*)tmv,
                                  (const float4*)tmr, (const float4*)tmg,
                                  (float4*)xk, (float4*)xv,
                                  (float4*)xr, (float4*)xg);
    }

    // 3) projections: r,k,v plain; g with silu
    dim3 gemm_grid(C_ / GBN, BT_ / GBM);   // (16, 128)
    gemm_tf32_kernel<<<gemm_grid, 128, GEMM_SMEM>>>(xr, w0, rr, 0);
    gemm_tf32_kernel<<<gemm_grid, 128, GEMM_SMEM>>>(xk, w1, kk, 0);
    gemm_tf32_kernel<<<gemm_grid, 128, GEMM_SMEM>>>(xv, w2, vv, 0);
    gemm_tf32_kernel<<<gemm_grid, 128, GEMM_SMEM>>>(xg, w3, gg, 1);

    // 4) WKV recurrence + fused /8 + groupnorm + *g  -> yng (tf32-rounded)
    wkv_kernel<<<B_ * H_ / 2, 512>>>(rr, kk, vv, gg, decay, faaaa, lnw, lnb, yng);

    // 5) output projection
    gemm_tf32_kernel<<<gemm_grid, 128, GEMM_SMEM>>>(yng, w4, (float*)d_out, 0);
}

// round 9
// speedup vs baseline: 3.0030x; 1.4509x over previous
#include <cuda_runtime.h>
#include <cuda_fp16.h>
#include <cstdint>
#include <cstddef>

#define B_   8
#define T_   2048
#define C_   2048
#define H_   32
#define BT_  (B_*T_)          // 16384
#define CC_  (C_*C_)
#define KU_  (C_/2)           // 1024 k-pair units

// ---------------- scratch (device globals; no allocation) ----------------
__device__ __half g_xk[BT_*(size_t)C_];
__device__ __half g_xv[BT_*(size_t)C_];
__device__ __half g_xr[BT_*(size_t)C_];
__device__ __half g_xg[BT_*(size_t)C_];
__device__ float  g_r [BT_*(size_t)C_];
__device__ float  g_k [BT_*(size_t)C_];
__device__ float  g_v [BT_*(size_t)C_];
__device__ float  g_g [BT_*(size_t)C_];
__device__ __half g_yng[BT_*(size_t)C_];
__device__ uint32_t g_W[5][KU_*(size_t)C_];   // packed half2(k even,k odd) x [n]

// ---------------- helpers ----------------
__device__ __forceinline__ uint32_t smem_u32(const void* p) {
    return (uint32_t)__cvta_generic_to_shared(p);
}
__device__ __forceinline__ uint32_t pack2(float a, float b) {
    __half2 h = __floats2half2_rn(a, b);
    return *(uint32_t*)&h;
}
__device__ __forceinline__ void mma_f16(float (&c)[4],
                                        const uint32_t (&a)[4],
                                        const uint32_t (&b)[2]) {
    asm volatile(
        "mma.sync.aligned.m16n8k16.row.col.f32.f16.f16.f32 "
        "{%0,%1,%2,%3}, {%4,%5,%6,%7}, {%8,%9}, {%0,%1,%2,%3};\n"
        : "+f"(c[0]), "+f"(c[1]), "+f"(c[2]), "+f"(c[3])
        : "r"(a[0]), "r"(a[1]), "r"(a[2]), "r"(a[3]),
          "r"(b[0]), "r"(b[1]));
}

// ---------------- weight prep: fp32 [K][N] -> packed fp16 [KU][N] ----------
__global__ void prep_w_kernel(const float* __restrict__ W,
                              uint32_t* __restrict__ Wp) {
    int idx = blockIdx.x * blockDim.x + threadIdx.x;
    if (idx >= KU_ * (C_ / 4)) return;
    int ku = idx >> 9;
    int n4 = (idx & 511) * 4;
    float4 r0 = *(const float4*)&W[(size_t)(2 * ku) * C_ + n4];
    float4 r1 = *(const float4*)&W[(size_t)(2 * ku + 1) * C_ + n4];
    uint4 o;
    o.x = pack2(r0.x, r1.x);
    o.y = pack2(r0.y, r1.y);
    o.z = pack2(r0.z, r1.z);
    o.w = pack2(r0.w, r1.w);
    *(uint4*)&Wp[(size_t)ku * C_ + n4] = o;
}

// ---------------- token-shift mix -> fp16 activations ------------------------
__global__ void mix_kernel(const float4* __restrict__ x,
                           const float4* __restrict__ tmk,
                           const float4* __restrict__ tmv,
                           const float4* __restrict__ tmr,
                           const float4* __restrict__ tmg,
                           __half* __restrict__ xk, __half* __restrict__ xv,
                           __half* __restrict__ xr, __half* __restrict__ xg) {
    const int C4 = C_ / 4;
    int idx = blockIdx.x * blockDim.x + threadIdx.x;
    if (idx >= BT_ * C4) return;
    int c4 = idx & (C4 - 1);
    int bt = idx >> 9;
    int t  = bt % T_;
    float4 xc = x[idx];
    float4 xp = make_float4(0.f, 0.f, 0.f, 0.f);
    if (t != 0) xp = x[idx - C4];
    float4 mk = tmk[c4], mv = tmv[c4], mr = tmr[c4], mg = tmg[c4];
    size_t ob = (size_t)bt * C_ + c4 * 4;
    uint2 u;
#define MIXC(dst, m) \
    u.x = pack2(fmaf(m.x, xc.x - xp.x, xp.x), fmaf(m.y, xc.y - xp.y, xp.y)); \
    u.y = pack2(fmaf(m.z, xc.z - xp.z, xp.z), fmaf(m.w, xc.w - xp.w, xp.w)); \
    *(uint2*)&dst[ob] = u;
    MIXC(xk, mk)
    MIXC(xv, mv)
    MIXC(xr, mr)
    MIXC(xg, mg)
#undef MIXC
}

// ---------------- fp16 mma.sync GEMM, warp tile 64x64 ------------------------
// C[16384,2048] = A[M,K]@B[K,N]; A fp16 row-major, B packed k-pair [KU][N].
// BM=BN=128, BK=32 (16 units), 4 stages, 128 threads (2x2 warps), m16n8k16.
#define GBM   128
#define GBN   128
#define NTIL  64
#define NSTG  4
#define AU    20                      // A row stride in u32 (16 + 4 pad)
#define BU    136                     // B row stride in u32 (128 + 8 pad)
#define A_U   (128 * AU)              // 2560
#define B_U   (16 * BU)               // 2176
#define STG_U (A_U + B_U)             // 4736
#define GEMM_SMEM (NSTG * STG_U * 4)  // 75776 bytes

__global__ __launch_bounds__(128, 2) void gemm_f16_kernel(
        const __half* __restrict__ Ag, const uint32_t* __restrict__ Bp,
        float* __restrict__ Cout, int act) {
    extern __shared__ uint32_t sm[];
    const uint32_t smb = smem_u32(sm);

    const int tid  = threadIdx.x;
    const int lane = tid & 31;
    const int warp = tid >> 5;
    const int wm = (warp >> 1) * 64;
    const int wn = (warp & 1) * 64;
    const int bm = blockIdx.y * GBM;
    const int bn = blockIdx.x * GBN;
    const int g  = lane >> 2;
    const int tt = lane & 3;

    float acc[4][8][4];
#pragma unroll
    for (int i = 0; i < 4; i++)
#pragma unroll
        for (int j = 0; j < 8; j++)
#pragma unroll
            for (int q = 0; q < 4; q++) acc[i][j][q] = 0.f;

    auto issue_tile = [&](int kt) {
        const int s = kt & (NSTG - 1);
        const uint32_t sA = smb + (uint32_t)(s * STG_U) * 4u;
        const uint32_t sB = sA + A_U * 4u;
#pragma unroll
        for (int q = 0; q < 4; q++) {           // A: 512 x 16B
            int f = tid + q * 128;
            int r  = f >> 2;
            int k4 = f & 3;
            const __half* gp = Ag + (size_t)(bm + r) * C_ + kt * 32 + k4 * 8;
            uint32_t so = sA + (uint32_t)(r * AU + k4 * 4) * 4u;
            asm volatile("cp.async.cg.shared.global [%0], [%1], 16;"
                         :: "r"(so), "l"(gp) : "memory");
        }
#pragma unroll
        for (int q = 0; q < 4; q++) {           // B: 512 x 16B
            int f = tid + q * 128;
            int kr = f >> 5;
            int n4 = f & 31;
            const uint32_t* gp = Bp + (size_t)(kt * 16 + kr) * C_ + bn + n4 * 4;
            uint32_t so = sB + (uint32_t)(kr * BU + n4 * 4) * 4u;
            asm volatile("cp.async.cg.shared.global [%0], [%1], 16;"
                         :: "r"(so), "l"(gp) : "memory");
        }
        asm volatile("cp.async.commit_group;" ::: "memory");
    };

    issue_tile(0);
    issue_tile(1);
    issue_tile(2);

#pragma unroll 1
    for (int kt = 0; kt < NTIL; kt++) {
        if (kt + NSTG - 1 < NTIL) {
            asm volatile("cp.async.wait_group %0;" :: "n"(NSTG - 2) : "memory");
        } else {
            asm volatile("cp.async.wait_group 0;" ::: "memory");
        }
        __syncthreads();
        if (kt + NSTG - 1 < NTIL) issue_tile(kt + NSTG - 1);

        const int s = kt & (NSTG - 1);
        const uint32_t* as = sm + s * STG_U;
        const uint32_t* bs = as + A_U;

#pragma unroll
        for (int ks = 0; ks < 2; ks++) {
            const int s8 = ks * 8;
            uint32_t af[4][4], bf[8][2];
#pragma unroll
            for (int mt = 0; mt < 4; mt++) {
                int rr = wm + mt * 16 + g;
                af[mt][0] = as[(rr)     * AU + s8 + tt];
                af[mt][1] = as[(rr + 8) * AU + s8 + tt];
                af[mt][2] = as[(rr)     * AU + s8 + tt + 4];
                af[mt][3] = as[(rr + 8) * AU + s8 + tt + 4];
            }
#pragma unroll
            for (int nt = 0; nt < 8; nt++) {
                int cb = wn + nt * 8 + g;
                bf[nt][0] = bs[(s8 + tt)     * BU + cb];
                bf[nt][1] = bs[(s8 + tt + 4) * BU + cb];
            }
#pragma unroll
            for (int mt = 0; mt < 4; mt++)
#pragma unroll
                for (int nt = 0; nt < 8; nt++)
                    mma_f16(acc[mt][nt], af[mt], bf[nt]);
        }
    }

#pragma unroll
    for (int mt = 0; mt < 4; mt++) {
#pragma unroll
        for (int nt = 0; nt < 8; nt++) {
            int row = bm + wm + mt * 16 + g;
            int col = bn + wn + nt * 8 + tt * 2;
            float v0 = acc[mt][nt][0], v1 = acc[mt][nt][1];
            float v2 = acc[mt][nt][2], v3 = acc[mt][nt][3];
            if (act == 1) {
                v0 = v0 / (1.f + expf(-v0));
                v1 = v1 / (1.f + expf(-v1));
                v2 = v2 / (1.f + expf(-v2));
                v3 = v3 / (1.f + expf(-v3));
            }
            *(float2*)&Cout[(size_t)row * C_ + col]       = make_float2(v0, v1);
            *(float2*)&Cout[(size_t)(row + 8) * C_ + col] = make_float2(v2, v3);
        }
    }
}

// ---------------- WKV5 recurrence + fused /8, groupnorm, *g -----------------
__global__ __launch_bounds__(512) void wkv_kernel(
        const float* __restrict__ r, const float* __restrict__ k,
        const float* __restrict__ v, const float* __restrict__ g,
        const float* __restrict__ decay, const float* __restrict__ faaaa,
        const float* __restrict__ lnw, const float* __restrict__ lnb,
        __half* __restrict__ yng) {
    __shared__ __align__(16) float sr[2][64];
    __shared__ __align__(16) float sk[2][64];
    __shared__ float sv[2][64];
    __shared__ float syp[2][256];
    __shared__ float sred[2][4];
    __shared__ float sruk[2][2];

    const int tid = threadIdx.x;
    const int hh  = tid >> 8;
    const int lt  = tid & 255;
    const int bh  = blockIdx.x * 2 + hh;
    const int b = bh / H_, h = bh % H_;
    const int ig = lt >> 6;
    const int j  = lt & 63;

    float S[16], w16[16];
#pragma unroll
    for (int ii = 0; ii < 16; ii++) {
        S[ii] = 0.f;
        w16[ii] = expf(-expf(decay[h * 64 + ig * 16 + ii]));
    }
    float uu = 0.f;
    if (lt >= 192) uu = faaaa[h * 64 + (lt - 192)];
    float lw = 1.f, lb = 0.f;
    if (lt < 64) { lw = lnw[h * 64 + lt]; lb = lnb[h * 64 + lt]; }

    size_t base = (size_t)b * T_ * C_ + (size_t)h * 64;
    const float inv_div = 1.f / 8.f;

    float pa = 0.f, pb = 0.f, pg = 0.f;
    if (lt < 64)       { pa = r[base + lt]; pg = g[base + lt]; }
    else if (lt < 128)   pa = k[base + (lt - 64)];
    else if (lt < 192)   pa = v[base + (lt - 128)];
    else               { pa = r[base + (lt - 192)]; pb = k[base + (lt - 192)]; }

    for (int t = 0; t < T_; t++) {
        if (lt < 64)       sr[hh][lt]       = pa;
        else if (lt < 128) sk[hh][lt - 64]  = pa;
        else if (lt < 192) sv[hh][lt - 128] = pa;
        else {
            float val = pa * uu * pb;
#pragma unroll
            for (int off = 16; off; off >>= 1)
                val += __shfl_xor_sync(0xffffffffu, val, off);
            if ((lt & 31) == 0) sruk[hh][(lt >> 5) & 1] = val;
        }
        const float gcur = pg;
        __syncthreads();

        if (t + 1 < T_) {
            size_t nb = base + C_;
            if (lt < 64)       { pa = r[nb + lt]; pg = g[nb + lt]; }
            else if (lt < 128)   pa = k[nb + (lt - 64)];
            else if (lt < 192)   pa = v[nb + (lt - 128)];
            else               { pa = r[nb + (lt - 192)]; pb = k[nb + (lt - 192)]; }
        }

        const float vj = sv[hh][j];
        const float4* r4 = (const float4*)&sr[hh][ig * 16];
        const float4* k4 = (const float4*)&sk[hh][ig * 16];
        float yp = 0.f;
#pragma unroll
        for (int q = 0; q < 4; q++) {
            float4 rv = r4[q];
            float4 kv = k4[q];
            yp = fmaf(rv.x, S[q*4+0], yp);
            S[q*4+0] = fmaf(w16[q*4+0], S[q*4+0], kv.x * vj);
            yp = fmaf(rv.y, S[q*4+1], yp);
            S[q*4+1] = fmaf(w16[q*4+1], S[q*4+1], kv.y * vj);
            yp = fmaf(rv.z, S[q*4+2], yp);
            S[q*4+2] = fmaf(w16[q*4+2], S[q*4+2], kv.z * vj);
            yp = fmaf(rv.w, S[q*4+3], yp);
            S[q*4+3] = fmaf(w16[q*4+3], S[q*4+3], kv.w * vj);
        }
        syp[hh][ig * 64 + j] = yp;
        __syncthreads();

        float yh = 0.f;
        if (lt < 64) {
            float ruk = sruk[hh][0] + sruk[hh][1];
            float y = syp[hh][j] + syp[hh][64 + j] + syp[hh][128 + j]
                    + syp[hh][192 + j] + ruk * sv[hh][j];
            yh = y * inv_div;
            float s1 = yh, s2 = yh * yh;
#pragma unroll
            for (int off = 16; off; off >>= 1) {
                s1 += __shfl_xor_sync(0xffffffffu, s1, off);
                s2 += __shfl_xor_sync(0xffffffffu, s2, off);
            }
            if ((lt & 31) == 0) {
                sred[hh][(lt >> 5) * 2]     = s1;
                sred[hh][(lt >> 5) * 2 + 1] = s2;
            }
        }
        __syncthreads();
        if (lt < 64) {
            float m1 = (sred[hh][0] + sred[hh][2]) * (1.f / 64.f);
            float m2 = (sred[hh][1] + sred[hh][3]) * (1.f / 64.f);
            float var = m2 - m1 * m1;
            float yn = (yh - m1) * rsqrtf(var + 1e-5f) * lw + lb;
            yng[base + lt] = __float2half(yn * gcur);
        }
        base += C_;
    }
}

// ---------------- host launch ----------------
extern "C" void kernel_launch(void* const* d_in, const int* in_sizes, int n_in,
                              void* d_out, int out_size) {
    const float* x     = (const float*)d_in[0];
    const float* tmk   = (const float*)d_in[1];
    const float* tmv   = (const float*)d_in[2];
    const float* tmr   = (const float*)d_in[3];
    const float* tmg   = (const float*)d_in[4];
    const float* decay = (const float*)d_in[5];
    const float* faaaa = (const float*)d_in[6];
    const float* Wr    = (const float*)d_in[7];
    const float* Wk    = (const float*)d_in[8];
    const float* Wv    = (const float*)d_in[9];
    const float* Wg    = (const float*)d_in[10];
    const float* Wo    = (const float*)d_in[11];
    const float* lnw   = (const float*)d_in[12];
    const float* lnb   = (const float*)d_in[13];

    __half *xk, *xv, *xr, *xg, *yng;
    float *rr, *kk, *vv, *gg;
    uint32_t* Wbuf;
    cudaGetSymbolAddress((void**)&xk,  g_xk);
    cudaGetSymbolAddress((void**)&xv,  g_xv);
    cudaGetSymbolAddress((void**)&xr,  g_xr);
    cudaGetSymbolAddress((void**)&xg,  g_xg);
    cudaGetSymbolAddress((void**)&rr,  g_r);
    cudaGetSymbolAddress((void**)&kk,  g_k);
    cudaGetSymbolAddress((void**)&vv,  g_v);
    cudaGetSymbolAddress((void**)&gg,  g_g);
    cudaGetSymbolAddress((void**)&yng, g_yng);
    cudaGetSymbolAddress((void**)&Wbuf, g_W);
    uint32_t* w0 = Wbuf + 0 * (size_t)(KU_ * (size_t)C_);
    uint32_t* w1 = Wbuf + 1 * (size_t)(KU_ * (size_t)C_);
    uint32_t* w2 = Wbuf + 2 * (size_t)(KU_ * (size_t)C_);
    uint32_t* w3 = Wbuf + 3 * (size_t)(KU_ * (size_t)C_);
    uint32_t* w4 = Wbuf + 4 * (size_t)(KU_ * (size_t)C_);

    cudaFuncSetAttribute(gemm_f16_kernel,
                         cudaFuncAttributeMaxDynamicSharedMemorySize, GEMM_SMEM);

    // 1) weights -> packed fp16 [KU][N]
    {
        int n = KU_ * (C_ / 4);
        int grid = (n + 255) / 256;
        prep_w_kernel<<<grid, 256>>>(Wr, w0);
        prep_w_kernel<<<grid, 256>>>(Wk, w1);
        prep_w_kernel<<<grid, 256>>>(Wv, w2);
        prep_w_kernel<<<grid, 256>>>(Wg, w3);
        prep_w_kernel<<<grid, 256>>>(Wo, w4);
    }

    // 2) token-shift mixes -> fp16
    {
        int n4 = BT_ * (C_ / 4);
        int grid = (n4 + 255) / 256;
        mix_kernel<<<grid, 256>>>((const float4*)x,
                                  (const float4*)tmk, (const float4*)tmv,
                                  (const float4*)tmr, (const float4*)tmg,
                                  xk, xv, xr, xg);
    }

    // 3) projections: r,k,v plain; g with silu
    dim3 gemm_grid(C_ / GBN, BT_ / GBM);   // (16, 128)
    gemm_f16_kernel<<<gemm_grid, 128, GEMM_SMEM>>>(xr, w0, rr, 0);
    gemm_f16_kernel<<<gemm_grid, 128, GEMM_SMEM>>>(xk, w1, kk, 0);
    gemm_f16_kernel<<<gemm_grid, 128, GEMM_SMEM>>>(xv, w2, vv, 0);
    gemm_f16_kernel<<<gemm_grid, 128, GEMM_SMEM>>>(xg, w3, gg, 1);

    // 4) WKV + /8 + groupnorm + *g -> fp16 yng
    wkv_kernel<<<B_ * H_ / 2, 512>>>(rr, kk, vv, gg, decay, faaaa, lnw, lnb, yng);

    // 5) output projection
    gemm_f16_kernel<<<gemm_grid, 128, GEMM_SMEM>>>(yng, w4, (float*)d_out, 0);
}

// round 10
// speedup vs baseline: 3.0552x; 1.0174x over previous
#include <cuda_runtime.h>
#include <cuda_fp16.h>
#include <cstdint>
#include <cstddef>

#define B_   8
#define T_   2048
#define C_   2048
#define H_   32
#define BT_  (B_*T_)          // 16384
#define KU_  (C_/2)           // 1024 k-pair units

// ---------------- scratch (device globals; no allocation) ----------------
__device__ __half g_xk[BT_*(size_t)C_];
__device__ __half g_xv[BT_*(size_t)C_];
__device__ __half g_xr[BT_*(size_t)C_];
__device__ __half g_xg[BT_*(size_t)C_];
__device__ float  g_r [BT_*(size_t)C_];
__device__ float  g_k [BT_*(size_t)C_];
__device__ float  g_v [BT_*(size_t)C_];
__device__ float  g_g [BT_*(size_t)C_];
__device__ __half g_yng[BT_*(size_t)C_];
__device__ uint32_t g_W[5][KU_*(size_t)C_];   // packed half2(k even,k odd) x [n]

// ---------------- helpers ----------------
__device__ __forceinline__ uint32_t smem_u32(const void* p) {
    return (uint32_t)__cvta_generic_to_shared(p);
}
__device__ __forceinline__ uint32_t pack2(float a, float b) {
    __half2 h = __floats2half2_rn(a, b);
    return *(uint32_t*)&h;
}
__device__ __forceinline__ void mma_f16(float (&c)[4],
                                        const uint32_t (&a)[4],
                                        const uint32_t (&b)[2]) {
    asm volatile(
        "mma.sync.aligned.m16n8k16.row.col.f32.f16.f16.f32 "
        "{%0,%1,%2,%3}, {%4,%5,%6,%7}, {%8,%9}, {%0,%1,%2,%3};\n"
        : "+f"(c[0]), "+f"(c[1]), "+f"(c[2]), "+f"(c[3])
        : "r"(a[0]), "r"(a[1]), "r"(a[2]), "r"(a[3]),
          "r"(b[0]), "r"(b[1]));
}

// ---------------- weight prep: fp32 [K][N] -> packed fp16 [KU][N] ----------
__global__ void prep_w_kernel(const float* __restrict__ W,
                              uint32_t* __restrict__ Wp) {
    int idx = blockIdx.x * blockDim.x + threadIdx.x;
    if (idx >= KU_ * (C_ / 4)) return;
    int ku = idx >> 9;
    int n4 = (idx & 511) * 4;
    float4 r0 = *(const float4*)&W[(size_t)(2 * ku) * C_ + n4];
    float4 r1 = *(const float4*)&W[(size_t)(2 * ku + 1) * C_ + n4];
    uint4 o;
    o.x = pack2(r0.x, r1.x);
    o.y = pack2(r0.y, r1.y);
    o.z = pack2(r0.z, r1.z);
    o.w = pack2(r0.w, r1.w);
    *(uint4*)&Wp[(size_t)ku * C_ + n4] = o;
}

// ---------------- token-shift mix -> fp16 activations ------------------------
__global__ void mix_kernel(const float4* __restrict__ x,
                           const float4* __restrict__ tmk,
                           const float4* __restrict__ tmv,
                           const float4* __restrict__ tmr,
                           const float4* __restrict__ tmg,
                           __half* __restrict__ xk, __half* __restrict__ xv,
                           __half* __restrict__ xr, __half* __restrict__ xg) {
    const int C4 = C_ / 4;
    int idx = blockIdx.x * blockDim.x + threadIdx.x;
    if (idx >= BT_ * C4) return;
    int c4 = idx & (C4 - 1);
    int bt = idx >> 9;
    int t  = bt % T_;
    float4 xc = x[idx];
    float4 xp = make_float4(0.f, 0.f, 0.f, 0.f);
    if (t != 0) xp = x[idx - C4];
    float4 mk = tmk[c4], mv = tmv[c4], mr = tmr[c4], mg = tmg[c4];
    size_t ob = (size_t)bt * C_ + c4 * 4;
    uint2 u;
#define MIXC(dst, m) \
    u.x = pack2(fmaf(m.x, xc.x - xp.x, xp.x), fmaf(m.y, xc.y - xp.y, xp.y)); \
    u.y = pack2(fmaf(m.z, xc.z - xp.z, xp.z), fmaf(m.w, xc.w - xp.w, xp.w)); \
    *(uint2*)&dst[ob] = u;
    MIXC(xk, mk)
    MIXC(xv, mv)
    MIXC(xr, mr)
    MIXC(xg, mg)
#undef MIXC
}

// ---------------- fp16 mma.sync GEMM, BK=64, warp tile 64x64 -----------------
// C[16384,2048] = A@B; A fp16 row-major, B packed k-pair [KU][N].
// BM=BN=128, BK=64 (32 u32 units), 3 stages, 128 threads (2x2 warps).
#define GBM   128
#define GBN   128
#define NTIL  32                      // 2048 / 64
#define NSTG  3
#define AU    36                      // A row stride in u32 (32 + 4 pad)
#define BU    136                     // B row stride in u32 (128 + 8 pad)
#define A_U   (128 * AU)              // 4608
#define B_U   (32 * BU)               // 4352
#define STG_U (A_U + B_U)             // 8960
#define GEMM_SMEM (NSTG * STG_U * 4)  // 107520 bytes

__global__ __launch_bounds__(128, 2) void gemm_f16_kernel(
        const __half* __restrict__ Ag, const uint32_t* __restrict__ Bp,
        float* __restrict__ Cout, int act) {
    extern __shared__ uint32_t sm[];
    const uint32_t smb = smem_u32(sm);

    const int tid  = threadIdx.x;
    const int lane = tid & 31;
    const int warp = tid >> 5;
    const int wm = (warp >> 1) * 64;
    const int wn = (warp & 1) * 64;
    const int bm = blockIdx.y * GBM;
    const int bn = blockIdx.x * GBN;
    const int g  = lane >> 2;
    const int tt = lane & 3;

    float acc[4][8][4];
#pragma unroll
    for (int i = 0; i < 4; i++)
#pragma unroll
        for (int j = 0; j < 8; j++)
#pragma unroll
            for (int q = 0; q < 4; q++) acc[i][j][q] = 0.f;

    auto issue_tile = [&](int kt) {
        const int s = kt % NSTG;
        const uint32_t sA = smb + (uint32_t)(s * STG_U) * 4u;
        const uint32_t sB = sA + A_U * 4u;
#pragma unroll
        for (int q = 0; q < 8; q++) {           // A: 1024 x 16B
            int f = tid + q * 128;
            int r  = f >> 3;                    // 0..127
            int k4 = f & 7;                     // 0..7
            const __half* gp = Ag + (size_t)(bm + r) * C_ + kt * 64 + k4 * 8;
            uint32_t so = sA + (uint32_t)(r * AU + k4 * 4) * 4u;
            asm volatile("cp.async.cg.shared.global [%0], [%1], 16;"
                         :: "r"(so), "l"(gp) : "memory");
        }
#pragma unroll
        for (int q = 0; q < 8; q++) {           // B: 1024 x 16B
            int f = tid + q * 128;
            int kr = f >> 5;                    // 0..31
            int n4 = f & 31;
            const uint32_t* gp = Bp + (size_t)(kt * 32 + kr) * C_ + bn + n4 * 4;
            uint32_t so = sB + (uint32_t)(kr * BU + n4 * 4) * 4u;
            asm volatile("cp.async.cg.shared.global [%0], [%1], 16;"
                         :: "r"(so), "l"(gp) : "memory");
        }
        asm volatile("cp.async.commit_group;" ::: "memory");
    };

    issue_tile(0);
    issue_tile(1);

#pragma unroll 1
    for (int kt = 0; kt < NTIL; kt++) {
        if (kt + NSTG - 1 < NTIL) {
            asm volatile("cp.async.wait_group 1;" ::: "memory");
        } else {
            asm volatile("cp.async.wait_group 0;" ::: "memory");
        }
        __syncthreads();
        if (kt + NSTG - 1 < NTIL) issue_tile(kt + NSTG - 1);

        const int s = kt % NSTG;
        const uint32_t* as = sm + s * STG_U;
        const uint32_t* bs = as + A_U;

#pragma unroll
        for (int ks = 0; ks < 4; ks++) {
            const int s8 = ks * 8;
            uint32_t af[4][4], bf[8][2];
#pragma unroll
            for (int mt = 0; mt < 4; mt++) {
                int rr = wm + mt * 16 + g;
                af[mt][0] = as[(rr)     * AU + s8 + tt];
                af[mt][1] = as[(rr + 8) * AU + s8 + tt];
                af[mt][2] = as[(rr)     * AU + s8 + tt + 4];
                af[mt][3] = as[(rr + 8) * AU + s8 + tt + 4];
            }
#pragma unroll
            for (int nt = 0; nt < 8; nt++) {
                int cb = wn + nt * 8 + g;
                bf[nt][0] = bs[(s8 + tt)     * BU + cb];
                bf[nt][1] = bs[(s8 + tt + 4) * BU + cb];
            }
#pragma unroll
            for (int mt = 0; mt < 4; mt++)
#pragma unroll
                for (int nt = 0; nt < 8; nt++)
                    mma_f16(acc[mt][nt], af[mt], bf[nt]);
        }
    }

#pragma unroll
    for (int mt = 0; mt < 4; mt++) {
#pragma unroll
        for (int nt = 0; nt < 8; nt++) {
            int row = bm + wm + mt * 16 + g;
            int col = bn + wn + nt * 8 + tt * 2;
            float v0 = acc[mt][nt][0], v1 = acc[mt][nt][1];
            float v2 = acc[mt][nt][2], v3 = acc[mt][nt][3];
            if (act == 1) {
                v0 = v0 / (1.f + expf(-v0));
                v1 = v1 / (1.f + expf(-v1));
                v2 = v2 / (1.f + expf(-v2));
                v3 = v3 / (1.f + expf(-v3));
            }
            *(float2*)&Cout[(size_t)row * C_ + col]       = make_float2(v0, v1);
            *(float2*)&Cout[(size_t)(row + 8) * C_ + col] = make_float2(v2, v3);
        }
    }
}

// ---------------- WKV5: 2 barriers/step, pipelined groupnorm ----------------
// 2 heads/CTA (512 threads). Per head: 256 threads = (ig 0..3) x (j 0..63).
// After syncB: warps 0-1 do groupnorm+store of step t (named barrier, 64 thr),
// warps 6-7 reduce ruk for t+1, all publish t+1 -> syncA. ruk*v folds into
// ig==0's yp during compute, so groupnorm never touches sv.
__global__ __launch_bounds__(512) void wkv_kernel(
        const float* __restrict__ r, const float* __restrict__ k,
        const float* __restrict__ v, const float* __restrict__ g,
        const float* __restrict__ decay, const float* __restrict__ faaaa,
        const float* __restrict__ lnw, const float* __restrict__ lnb,
        __half* __restrict__ yng) {
    __shared__ __align__(16) float sr[2][64];
    __shared__ __align__(16) float sk[2][64];
    __shared__ float sv[2][64];
    __shared__ float syp[2][256];
    __shared__ float sred[2][4];
    __shared__ float sruk[2][2][2];   // [buf][head][warp-partial]

    const int tid = threadIdx.x;
    const int hh  = tid >> 8;
    const int lt  = tid & 255;
    const int bh  = blockIdx.x * 2 + hh;
    const int b = bh / H_, h = bh % H_;
    const int ig = lt >> 6;
    const int j  = lt & 63;

    float S[16], w16[16];
#pragma unroll
    for (int ii = 0; ii < 16; ii++) {
        S[ii] = 0.f;
        w16[ii] = expf(-expf(decay[h * 64 + ig * 16 + ii]));
    }
    float uu = 0.f;
    if (lt >= 192) uu = faaaa[h * 64 + (lt - 192)];
    float lw = 1.f, lb = 0.f;
    if (lt < 64) { lw = lnw[h * 64 + lt]; lb = lnb[h * 64 + lt]; }

    size_t base = (size_t)b * T_ * C_ + (size_t)h * 64;

    // prefetch + publish t = 0
    float pa = 0.f, pb = 0.f, pg = 0.f;
    if (lt < 64)       { pa = r[base + lt]; pg = g[base + lt]; }
    else if (lt < 128)   pa = k[base + (lt - 64)];
    else if (lt < 192)   pa = v[base + (lt - 128)];
    else               { pa = r[base + (lt - 192)]; pb = k[base + (lt - 192)]; }

    if (lt < 64)       sr[hh][lt]       = pa;
    else if (lt < 128) sk[hh][lt - 64]  = pa;
    else if (lt < 192) sv[hh][lt - 128] = pa;
    else {
        float val = pa * uu * pb;
#pragma unroll
        for (int off = 16; off; off >>= 1)
            val += __shfl_xor_sync(0xffffffffu, val, off);
        if ((lt & 31) == 0) sruk[0][hh][(lt >> 5) & 1] = val;
    }
    __syncthreads();   // A: step-0 operands visible

    for (int t = 0; t < T_; t++) {
        const float gcur = pg;
        // prefetch t+1
        if (t + 1 < T_) {
            size_t nb = base + C_;
            if (lt < 64)       { pa = r[nb + lt]; pg = g[nb + lt]; }
            else if (lt < 128)   pa = k[nb + (lt - 64)];
            else if (lt < 192)   pa = v[nb + (lt - 128)];
            else               { pa = r[nb + (lt - 192)]; pb = k[nb + (lt - 192)]; }
        }

        // compute y partials + state update
        const float vj = sv[hh][j];
        float yp0 = 0.f, yp1 = 0.f, yp2 = 0.f, yp3 = 0.f;
        if (ig == 0)
            yp0 = (sruk[t & 1][hh][0] + sruk[t & 1][hh][1]) * vj;
        const float4* r4 = (const float4*)&sr[hh][ig * 16];
        const float4* k4 = (const float4*)&sk[hh][ig * 16];
#pragma unroll
        for (int q = 0; q < 4; q++) {
            float4 rv = r4[q];
            float4 kv = k4[q];
            yp0 = fmaf(rv.x, S[q*4+0], yp0);
            S[q*4+0] = fmaf(w16[q*4+0], S[q*4+0], kv.x * vj);
            yp1 = fmaf(rv.y, S[q*4+1], yp1);
            S[q*4+1] = fmaf(w16[q*4+1], S[q*4+1], kv.y * vj);
            yp2 = fmaf(rv.z, S[q*4+2], yp2);
            S[q*4+2] = fmaf(w16[q*4+2], S[q*4+2], kv.z * vj);
            yp3 = fmaf(rv.w, S[q*4+3], yp3);
            S[q*4+3] = fmaf(w16[q*4+3], S[q*4+3], kv.w * vj);
        }
        syp[hh][ig * 64 + j] = (yp0 + yp1) + (yp2 + yp3);
        __syncthreads();   // B: syp complete, sr/sk/sv free

        // window: publish t+1, ruk(t+1), groupnorm(t) in parallel warps
        if (t + 1 < T_) {
            if (lt < 64)       sr[hh][lt]       = pa;
            else if (lt < 128) sk[hh][lt - 64]  = pa;
            else if (lt < 192) sv[hh][lt - 128] = pa;
            else {
                float val = pa * uu * pb;
#pragma unroll
                for (int off = 16; off; off >>= 1)
                    val += __shfl_xor_sync(0xffffffffu, val, off);
                if ((lt & 31) == 0) sruk[(t + 1) & 1][hh][(lt >> 5) & 1] = val;
            }
        }
        if (lt < 64) {
            float y = syp[hh][j] + syp[hh][64 + j] + syp[hh][128 + j]
                    + syp[hh][192 + j];
            float yh = y * 0.125f;
            float s1 = yh, s2 = yh * yh;
#pragma unroll
            for (int off = 16; off; off >>= 1) {
                s1 += __shfl_xor_sync(0xffffffffu, s1, off);
                s2 += __shfl_xor_sync(0xffffffffu, s2, off);
            }
            if ((lt & 31) == 0) {
                sred[hh][(lt >> 5) * 2]     = s1;
                sred[hh][(lt >> 5) * 2 + 1] = s2;
            }
            asm volatile("bar.sync %0, 64;" :: "r"(1 + hh) : "memory");
            float m1 = (sred[hh][0] + sred[hh][2]) * (1.f / 64.f);
            float m2 = (sred[hh][1] + sred[hh][3]) * (1.f / 64.f);
            float var = m2 - m1 * m1;
            float yn = (yh - m1) * rsqrtf(var + 1e-5f) * lw + lb;
            yng[base + lt] = __float2half(yn * gcur);
        }
        __syncthreads();   // A: t+1 operands visible, sred/syp reusable
        base += C_;
    }
}

// ---------------- host launch ----------------
extern "C" void kernel_launch(void* const* d_in, const int* in_sizes, int n_in,
                              void* d_out, int out_size) {
    const float* x     = (const float*)d_in[0];
    const float* tmk   = (const float*)d_in[1];
    const float* tmv   = (const float*)d_in[2];
    const float* tmr   = (const float*)d_in[3];
    const float* tmg   = (const float*)d_in[4];
    const float* decay = (const float*)d_in[5];
    const float* faaaa = (const float*)d_in[6];
    const float* Wr    = (const float*)d_in[7];
    const float* Wk    = (const float*)d_in[8];
    const float* Wv    = (const float*)d_in[9];
    const float* Wg    = (const float*)d_in[10];
    const float* Wo    = (const float*)d_in[11];
    const float* lnw   = (const float*)d_in[12];
    const float* lnb   = (const float*)d_in[13];

    __half *xk, *xv, *xr, *xg, *yng;
    float *rr, *kk, *vv, *gg;
    uint32_t* Wbuf;
    cudaGetSymbolAddress((void**)&xk,  g_xk);
    cudaGetSymbolAddress((void**)&xv,  g_xv);
    cudaGetSymbolAddress((void**)&xr,  g_xr);
    cudaGetSymbolAddress((void**)&xg,  g_xg);
    cudaGetSymbolAddress((void**)&rr,  g_r);
    cudaGetSymbolAddress((void**)&kk,  g_k);
    cudaGetSymbolAddress((void**)&vv,  g_v);
    cudaGetSymbolAddress((void**)&gg,  g_g);
    cudaGetSymbolAddress((void**)&yng, g_yng);
    cudaGetSymbolAddress((void**)&Wbuf, g_W);
    uint32_t* w0 = Wbuf + 0 * (size_t)(KU_ * (size_t)C_);
    uint32_t* w1 = Wbuf + 1 * (size_t)(KU_ * (size_t)C_);
    uint32_t* w2 = Wbuf + 2 * (size_t)(KU_ * (size_t)C_);
    uint32_t* w3 = Wbuf + 3 * (size_t)(KU_ * (size_t)C_);
    uint32_t* w4 = Wbuf + 4 * (size_t)(KU_ * (size_t)C_);

    cudaFuncSetAttribute(gemm_f16_kernel,
                         cudaFuncAttributeMaxDynamicSharedMemorySize, GEMM_SMEM);

    // 1) weights -> packed fp16 [KU][N]
    {
        int n = KU_ * (C_ / 4);
        int grid = (n + 255) / 256;
        prep_w_kernel<<<grid, 256>>>(Wr, w0);
        prep_w_kernel<<<grid, 256>>>(Wk, w1);
        prep_w_kernel<<<grid, 256>>>(Wv, w2);
        prep_w_kernel<<<grid, 256>>>(Wg, w3);
        prep_w_kernel<<<grid, 256>>>(Wo, w4);
    }

    // 2) token-shift mixes -> fp16
    {
        int n4 = BT_ * (C_ / 4);
        int grid = (n4 + 255) / 256;
        mix_kernel<<<grid, 256>>>((const float4*)x,
                                  (const float4*)tmk, (const float4*)tmv,
                                  (const float4*)tmr, (const float4*)tmg,
                                  xk, xv, xr, xg);
    }

    // 3) projections: r,k,v plain; g with silu
    dim3 gemm_grid(C_ / GBN, BT_ / GBM);   // (16, 128)
    gemm_f16_kernel<<<gemm_grid, 128, GEMM_SMEM>>>(xr, w0, rr, 0);
    gemm_f16_kernel<<<gemm_grid, 128, GEMM_SMEM>>>(xk, w1, kk, 0);
    gemm_f16_kernel<<<gemm_grid, 128, GEMM_SMEM>>>(xv, w2, vv, 0);
    gemm_f16_kernel<<<gemm_grid, 128, GEMM_SMEM>>>(xg, w3, gg, 1);

    // 4) WKV + /8 + groupnorm + *g -> fp16 yng
    wkv_kernel<<<B_ * H_ / 2, 512>>>(rr, kk, vv, gg, decay, faaaa, lnw, lnb, yng);

    // 5) output projection
    gemm_f16_kernel<<<gemm_grid, 128, GEMM_SMEM>>>(yng, w4, (float*)d_out, 0);
}

// round 13
// speedup vs baseline: 3.5868x; 1.1740x over previous
#include <cuda_runtime.h>
#include <cuda_fp16.h>
#include <cstdint>
#include <cstddef>

#define B_   8
#define T_   2048
#define C_   2048
#define H_   32
#define BT_  (B_*T_)          // 16384
#define KU_  (C_/2)           // 1024 k-pair units

// ---------------- scratch (device globals; no allocation) ----------------
__device__ __half g_xk[BT_*(size_t)C_];
__device__ __half g_xv[BT_*(size_t)C_];
__device__ __half g_xr[BT_*(size_t)C_];
__device__ __half g_xg[BT_*(size_t)C_];
__device__ float  g_r [BT_*(size_t)C_];
__device__ float  g_k [BT_*(size_t)C_];
__device__ float  g_v [BT_*(size_t)C_];
__device__ float  g_g [BT_*(size_t)C_];
__device__ __half g_yng[BT_*(size_t)C_];
__device__ uint32_t g_W[5][KU_*(size_t)C_];   // packed half2(k even,k odd) x [n]

// ---------------- helpers ----------------
__device__ __forceinline__ uint32_t smem_u32(const void* p) {
    return (uint32_t)__cvta_generic_to_shared(p);
}
__device__ __forceinline__ uint32_t pack2(float a, float b) {
    __half2 h = __floats2half2_rn(a, b);
    return *(uint32_t*)&h;
}
__device__ __forceinline__ void mma_f16(float (&c)[4],
                                        const uint32_t (&a)[4],
                                        const uint32_t (&b)[2]) {
    asm volatile(
        "mma.sync.aligned.m16n8k16.row.col.f32.f16.f16.f32 "
        "{%0,%1,%2,%3}, {%4,%5,%6,%7}, {%8,%9}, {%0,%1,%2,%3};\n"
        : "+f"(c[0]), "+f"(c[1]), "+f"(c[2]), "+f"(c[3])
        : "r"(a[0]), "r"(a[1]), "r"(a[2]), "r"(a[3]),
          "r"(b[0]), "r"(b[1]));
}

// ---------------- weight prep: all 5 weights in one launch -------------------
__global__ void prep_w_kernel(const float* __restrict__ W0,
                              const float* __restrict__ W1,
                              const float* __restrict__ W2,
                              const float* __restrict__ W3,
                              const float* __restrict__ W4,
                              uint32_t* __restrict__ Wp) {
    int idx = blockIdx.x * blockDim.x + threadIdx.x;
    if (idx >= KU_ * (C_ / 4)) return;
    const float* W = (blockIdx.y == 0) ? W0 : (blockIdx.y == 1) ? W1 :
                     (blockIdx.y == 2) ? W2 : (blockIdx.y == 3) ? W3 : W4;
    uint32_t* Wo = Wp + (size_t)blockIdx.y * (KU_ * (size_t)C_);
    int ku = idx >> 9;
    int n4 = (idx & 511) * 4;
    float4 r0 = *(const float4*)&W[(size_t)(2 * ku) * C_ + n4];
    float4 r1 = *(const float4*)&W[(size_t)(2 * ku + 1) * C_ + n4];
    uint4 o;
    o.x = pack2(r0.x, r1.x);
    o.y = pack2(r0.y, r1.y);
    o.z = pack2(r0.z, r1.z);
    o.w = pack2(r0.w, r1.w);
    *(uint4*)&Wo[(size_t)ku * C_ + n4] = o;
}

// ---------------- token-shift mix -> fp16 activations ------------------------
__global__ void mix_kernel(const float4* __restrict__ x,
                           const float4* __restrict__ tmk,
                           const float4* __restrict__ tmv,
                           const float4* __restrict__ tmr,
                           const float4* __restrict__ tmg,
                           __half* __restrict__ xk, __half* __restrict__ xv,
                           __half* __restrict__ xr, __half* __restrict__ xg) {
    const int C4 = C_ / 4;
    int idx = blockIdx.x * blockDim.x + threadIdx.x;
    if (idx >= BT_ * C4) return;
    int c4 = idx & (C4 - 1);
    int bt = idx >> 9;
    int t  = bt % T_;
    float4 xc = x[idx];
    float4 xp = make_float4(0.f, 0.f, 0.f, 0.f);
    if (t != 0) xp = x[idx - C4];
    float4 mk = tmk[c4], mv = tmv[c4], mr = tmr[c4], mg = tmg[c4];
    size_t ob = (size_t)bt * C_ + c4 * 4;
    uint2 u;
#define MIXC(dst, m) \
    u.x = pack2(fmaf(m.x, xc.x - xp.x, xp.x), fmaf(m.y, xc.y - xp.y, xp.y)); \
    u.y = pack2(fmaf(m.z, xc.z - xp.z, xp.z), fmaf(m.w, xc.w - xp.w, xp.w)); \
    *(uint2*)&dst[ob] = u;
    MIXC(xk, mk)
    MIXC(xv, mv)
    MIXC(xr, mr)
    MIXC(xg, mg)
#undef MIXC
}

// ---------------- fp16 mma.sync GEMM, BK=64, warp tile 64x64 -----------------
#define GBM   128
#define GBN   128
#define NTIL  32                      // 2048 / 64
#define NSTG  3
#define AU    36
#define BU    136
#define A_U   (128 * AU)              // 4608
#define B_U   (32 * BU)               // 4352
#define STG_U (A_U + B_U)             // 8960
#define GEMM_SMEM (NSTG * STG_U * 4)  // 107520 bytes

__global__ __launch_bounds__(128, 2) void gemm_f16_kernel(
        const __half* __restrict__ Ag, const uint32_t* __restrict__ Bp,
        float* __restrict__ Cout, int act) {
    extern __shared__ uint32_t sm[];
    const uint32_t smb = smem_u32(sm);

    const int tid  = threadIdx.x;
    const int lane = tid & 31;
    const int warp = tid >> 5;
    const int wm = (warp >> 1) * 64;
    const int wn = (warp & 1) * 64;
    const int bm = blockIdx.y * GBM;
    const int bn = blockIdx.x * GBN;
    const int g  = lane >> 2;
    const int tt = lane & 3;

    float acc[4][8][4];
#pragma unroll
    for (int i = 0; i < 4; i++)
#pragma unroll
        for (int j = 0; j < 8; j++)
#pragma unroll
            for (int q = 0; q < 4; q++) acc[i][j][q] = 0.f;

    auto issue_tile = [&](int kt) {
        const int s = kt % NSTG;
        const uint32_t sA = smb + (uint32_t)(s * STG_U) * 4u;
        const uint32_t sB = sA + A_U * 4u;
#pragma unroll
        for (int q = 0; q < 8; q++) {
            int f = tid + q * 128;
            int r  = f >> 3;
            int k4 = f & 7;
            const __half* gp = Ag + (size_t)(bm + r) * C_ + kt * 64 + k4 * 8;
            uint32_t so = sA + (uint32_t)(r * AU + k4 * 4) * 4u;
            asm volatile("cp.async.cg.shared.global [%0], [%1], 16;"
                         :: "r"(so), "l"(gp) : "memory");
        }
#pragma unroll
        for (int q = 0; q < 8; q++) {
            int f = tid + q * 128;
            int kr = f >> 5;
            int n4 = f & 31;
            const uint32_t* gp = Bp + (size_t)(kt * 32 + kr) * C_ + bn + n4 * 4;
            uint32_t so = sB + (uint32_t)(kr * BU + n4 * 4) * 4u;
            asm volatile("cp.async.cg.shared.global [%0], [%1], 16;"
                         :: "r"(so), "l"(gp) : "memory");
        }
        asm volatile("cp.async.commit_group;" ::: "memory");
    };

    issue_tile(0);
    issue_tile(1);

#pragma unroll 1
    for (int kt = 0; kt < NTIL; kt++) {
        if (kt + NSTG - 1 < NTIL) {
            asm volatile("cp.async.wait_group 1;" ::: "memory");
        } else {
            asm volatile("cp.async.wait_group 0;" ::: "memory");
        }
        __syncthreads();
        if (kt + NSTG - 1 < NTIL) issue_tile(kt + NSTG - 1);

        const int s = kt % NSTG;
        const uint32_t* as = sm + s * STG_U;
        const uint32_t* bs = as + A_U;

#pragma unroll
        for (int ks = 0; ks < 4; ks++) {
            const int s8 = ks * 8;
            uint32_t af[4][4], bf[8][2];
#pragma unroll
            for (int mt = 0; mt < 4; mt++) {
                int rr = wm + mt * 16 + g;
                af[mt][0] = as[(rr)     * AU + s8 + tt];
                af[mt][1] = as[(rr + 8) * AU + s8 + tt];
                af[mt][2] = as[(rr)     * AU + s8 + tt + 4];
                af[mt][3] = as[(rr + 8) * AU + s8 + tt + 4];
            }
#pragma unroll
            for (int nt = 0; nt < 8; nt++) {
                int cb = wn + nt * 8 + g;
                bf[nt][0] = bs[(s8 + tt)     * BU + cb];
                bf[nt][1] = bs[(s8 + tt + 4) * BU + cb];
            }
#pragma unroll
            for (int mt = 0; mt < 4; mt++)
#pragma unroll
                for (int nt = 0; nt < 8; nt++)
                    mma_f16(acc[mt][nt], af[mt], bf[nt]);
        }
    }

#pragma unroll
    for (int mt = 0; mt < 4; mt++) {
#pragma unroll
        for (int nt = 0; nt < 8; nt++) {
            int row = bm + wm + mt * 16 + g;
            int col = bn + wn + nt * 8 + tt * 2;
            float v0 = acc[mt][nt][0], v1 = acc[mt][nt][1];
            float v2 = acc[mt][nt][2], v3 = acc[mt][nt][3];
            if (act == 1) {
                v0 = v0 / (1.f + expf(-v0));
                v1 = v1 / (1.f + expf(-v1));
                v2 = v2 / (1.f + expf(-v2));
                v3 = v3 / (1.f + expf(-v3));
            }
            *(float2*)&Cout[(size_t)row * C_ + col]       = make_float2(v0, v1);
            *(float2*)&Cout[(size_t)(row + 8) * C_ + col] = make_float2(v2, v3);
        }
    }
}

// ---------------- WKV5: chunked smem staging, 1 barrier/step ----------------
// 2 heads/CTA (512 thr), 128 CTAs. CH=8 steps per chunk, cp.async double-
// buffered 2 chunks ahead. Per head 256 thr = (ig 0..3) x (j 0..63).
// ruk scalars for the whole chunk are precomputed at chunk entry (warps 6-7).
// syp ping-pongs on step parity -> one __syncthreads per step.
#define CH    8
#define NCHK  (T_/CH)    // 256

__global__ __launch_bounds__(512) void wkv_kernel(
        const float* __restrict__ r, const float* __restrict__ k,
        const float* __restrict__ v, const float* __restrict__ g,
        const float* __restrict__ decay, const float* __restrict__ faaaa,
        const float* __restrict__ lnw, const float* __restrict__ lnb,
        __half* __restrict__ yng) {
    __shared__ __align__(16) float sbuf[2][2][4][CH][64]; // [hh][p][r,k,v,g][t][i]
    __shared__ float syp[2][2][256];                      // [hh][parity][.]
    __shared__ float sred[2][4];
    __shared__ float sruk[2][2][CH];                      // [p][hh][t]

    const int tid = threadIdx.x;
    const int hh  = tid >> 8;
    const int lt  = tid & 255;
    const int lane = lt & 31;
    const int bh  = blockIdx.x * 2 + hh;
    const int b = bh / H_, h = bh % H_;
    const int ig = lt >> 6;
    const int j  = lt & 63;

    float S[16], w16[16];
#pragma unroll
    for (int ii = 0; ii < 16; ii++) {
        S[ii] = 0.f;
        w16[ii] = expf(-expf(decay[h * 64 + ig * 16 + ii]));
    }
    float u1 = 0.f, u2 = 0.f;
    if (lt >= 192) {
        u1 = faaaa[h * 64 + lane];
        u2 = faaaa[h * 64 + lane + 32];
    }
    float lw = 1.f, lb = 0.f;
    if (lt < 64) { lw = lnw[h * 64 + lt]; lb = lnb[h * 64 + lt]; }

    const size_t base = (size_t)b * T_ * C_ + (size_t)h * 64;
    const float* aptr[4] = { r + base, k + base, v + base, g + base };

    auto issue_chunk = [&](int c) {
        const int p = c & 1;
#pragma unroll
        for (int q = 0; q < 2; q++) {
            int f = lt + q * 256;          // 0..511
            int arr = f >> 7;              // 0..3
            int t   = (f >> 4) & 7;
            int i4  = f & 15;
            const float* gp = aptr[arr] + (size_t)(c * CH + t) * C_ + i4 * 4;
            uint32_t so = smem_u32(&sbuf[hh][p][arr][t][i4 * 4]);
            asm volatile("cp.async.cg.shared.global [%0], [%1], 16;"
                         :: "r"(so), "l"(gp) : "memory");
        }
        asm volatile("cp.async.commit_group;" ::: "memory");
    };

    issue_chunk(0);
    issue_chunk(1);

    for (int c = 0; c < NCHK; c++) {
        const int p = c & 1;
        if (c + 1 < NCHK) {
            asm volatile("cp.async.wait_group 1;" ::: "memory");
        } else {
            asm volatile("cp.async.wait_group 0;" ::: "memory");
        }
        __syncthreads();                    // chunk data visible

        // precompute ruk for all CH steps (warps 6-7 per head)
        if (lt >= 192) {
            int w = (lt >> 5) - 6;          // 0 or 1
#pragma unroll
            for (int s = 0; s < 4; s++) {
                int t = w * 4 + s;
                float val = sbuf[hh][p][0][t][lane] * u1 * sbuf[hh][p][1][t][lane]
                          + sbuf[hh][p][0][t][lane + 32] * u2 * sbuf[hh][p][1][t][lane + 32];
#pragma unroll
                for (int off = 16; off; off >>= 1)
                    val += __shfl_xor_sync(0xffffffffu, val, off);
                if (lane == 0) sruk[p][hh][t] = val;
            }
        }
        __syncthreads();                    // ruk visible

#pragma unroll 1
        for (int t = 0; t < CH; t++) {
            const int ts = c * CH + t;
            const float vj = sbuf[hh][p][2][t][j];
            const float gv = sbuf[hh][p][3][t][j];   // read pre-barrier
            float yp0 = 0.f, yp1 = 0.f, yp2 = 0.f, yp3 = 0.f;
            if (ig == 0) yp0 = sruk[p][hh][t] * vj;
            const float4* r4 = (const float4*)&sbuf[hh][p][0][t][ig * 16];
            const float4* k4 = (const float4*)&sbuf[hh][p][1][t][ig * 16];
#pragma unroll
            for (int q = 0; q < 4; q++) {
                float4 rv = r4[q];
                float4 kv = k4[q];
                yp0 = fmaf(rv.x, S[q*4+0], yp0);
                S[q*4+0] = fmaf(w16[q*4+0], S[q*4+0], kv.x * vj);
                yp1 = fmaf(rv.y, S[q*4+1], yp1);
                S[q*4+1] = fmaf(w16[q*4+1], S[q*4+1], kv.y * vj);
                yp2 = fmaf(rv.z, S[q*4+2], yp2);
                S[q*4+2] = fmaf(w16[q*4+2], S[q*4+2], kv.z * vj);
                yp3 = fmaf(rv.w, S[q*4+3], yp3);
                S[q*4+3] = fmaf(w16[q*4+3], S[q*4+3], kv.w * vj);
            }
            syp[hh][ts & 1][ig * 64 + j] = (yp0 + yp1) + (yp2 + yp3);
            __syncthreads();                // syp(t) complete

            if (lt < 64) {                  // groupnorm(t), overlapped with
                const float* sp = syp[hh][ts & 1];      // others' next compute
                float y = sp[lt] + sp[64 + lt] + sp[128 + lt] + sp[192 + lt];
                float yh = y * 0.125f;
                float s1 = yh, s2 = yh * yh;
#pragma unroll
                for (int off = 16; off; off >>= 1) {
                    s1 += __shfl_xor_sync(0xffffffffu, s1, off);
                    s2 += __shfl_xor_sync(0xffffffffu, s2, off);
                }
                if (lane == 0) {
                    sred[hh][(lt >> 5) * 2]     = s1;
                    sred[hh][(lt >> 5) * 2 + 1] = s2;
                }
                asm volatile("bar.sync %0, 64;" :: "r"(1 + hh) : "memory");
                float m1 = (sred[hh][0] + sred[hh][2]) * (1.f / 64.f);
                float m2 = (sred[hh][1] + sred[hh][3]) * (1.f / 64.f);
                float var = m2 - m1 * m1;
                float yn = (yh - m1) * rsqrtf(var + 1e-5f) * lw + lb;
                yng[base + (size_t)ts * C_ + lt] = __float2half(yn * gv);
            }
        }
        if (c + 2 < NCHK) issue_chunk(c + 2);
    }
}

// ---------------- host launch ----------------
extern "C" void kernel_launch(void* const* d_in, const int* in_sizes, int n_in,
                              void* d_out, int out_size) {
    const float* x     = (const float*)d_in[0];
    const float* tmk   = (const float*)d_in[1];
    const float* tmv   = (const float*)d_in[2];
    const float* tmr   = (const float*)d_in[3];
    const float* tmg   = (const float*)d_in[4];
    const float* decay = (const float*)d_in[5];
    const float* faaaa = (const float*)d_in[6];
    const float* Wr    = (const float*)d_in[7];
    const float* Wk    = (const float*)d_in[8];
    const float* Wv    = (const float*)d_in[9];
    const float* Wg    = (const float*)d_in[10];
    const float* Wo    = (const float*)d_in[11];
    const float* lnw   = (const float*)d_in[12];
    const float* lnb   = (const float*)d_in[13];

    __half *xk, *xv, *xr, *xg, *yng;
    float *rr, *kk, *vv, *gg;
    uint32_t* Wbuf;
    cudaGetSymbolAddress((void**)&xk,  g_xk);
    cudaGetSymbolAddress((void**)&xv,  g_xv);
    cudaGetSymbolAddress((void**)&xr,  g_xr);
    cudaGetSymbolAddress((void**)&xg,  g_xg);
    cudaGetSymbolAddress((void**)&rr,  g_r);
    cudaGetSymbolAddress((void**)&kk,  g_k);
    cudaGetSymbolAddress((void**)&vv,  g_v);
    cudaGetSymbolAddress((void**)&gg,  g_g);
    cudaGetSymbolAddress((void**)&yng, g_yng);
    cudaGetSymbolAddress((void**)&Wbuf, g_W);
    uint32_t* w0 = Wbuf + 0 * (size_t)(KU_ * (size_t)C_);
    uint32_t* w1 = Wbuf + 1 * (size_t)(KU_ * (size_t)C_);
    uint32_t* w2 = Wbuf + 2 * (size_t)(KU_ * (size_t)C_);
    uint32_t* w3 = Wbuf + 3 * (size_t)(KU_ * (size_t)C_);
    uint32_t* w4 = Wbuf + 4 * (size_t)(KU_ * (size_t)C_);

    cudaFuncSetAttribute(gemm_f16_kernel,
                         cudaFuncAttributeMaxDynamicSharedMemorySize, GEMM_SMEM);

    // 1) weights -> packed fp16 [KU][N] (single launch, 5 weights)
    {
        int n = KU_ * (C_ / 4);
        dim3 grid((n + 255) / 256, 5);
        prep_w_kernel<<<grid, 256>>>(Wr, Wk, Wv, Wg, Wo, Wbuf);
    }

    // 2) token-shift mixes -> fp16
    {
        int n4 = BT_ * (C_ / 4);
        int grid = (n4 + 255) / 256;
        mix_kernel<<<grid, 256>>>((const float4*)x,
                                  (const float4*)tmk, (const float4*)tmv,
                                  (const float4*)tmr, (const float4*)tmg,
                                  xk, xv, xr, xg);
    }

    // 3) projections: r,k,v plain; g with silu
    dim3 gemm_grid(C_ / GBN, BT_ / GBM);   // (16, 128)
    gemm_f16_kernel<<<gemm_grid, 128, GEMM_SMEM>>>(xr, w0, rr, 0);
    gemm_f16_kernel<<<gemm_grid, 128, GEMM_SMEM>>>(xk, w1, kk, 0);
    gemm_f16_kernel<<<gemm_grid, 128, GEMM_SMEM>>>(xv, w2, vv, 0);
    gemm_f16_kernel<<<gemm_grid, 128, GEMM_SMEM>>>(xg, w3, gg, 1);

    // 4) WKV + /8 + groupnorm + *g -> fp16 yng
    wkv_kernel<<<B_ * H_ / 2, 512>>>(rr, kk, vv, gg, decay, faaaa, lnw, lnb, yng);

    // 5) output projection
    gemm_f16_kernel<<<gemm_grid, 128, GEMM_SMEM>>>(yng, w4, (float*)d_out, 0);
}